// round 10
// baseline (speedup 1.0000x reference)
#include <cuda_runtime.h>
#include <math.h>
#include <stdint.h>

// Problem constants
#define BB    16
#define B2    32
#define TT    500
#define HH    1024
#define GG    2048
#define NROWS 16000
#define HS    (HH * B2)

typedef unsigned long long ull;

// ---------------- scratch (device globals; no allocation) ----------------
__device__ __align__(128) float g_w  [(size_t)NROWS * GG];   // raw input projections [r][g]
__device__ __align__(128) float g_wT [(size_t)TT * GG * B2]; // normalized, [t][g][b2]
__device__ __align__(128) float g_hs0[(size_t)B2 * TT * HH]; // layer-0 hidden sequence
__device__ __align__(128) float g_h  [2 * HS];               // double-buffered h, [parity][k][b]
__device__ __align__(128) float g_psum[125 * GG];
__device__ __align__(128) float g_psq [125 * GG];
__device__ float g_scale[GG];
__device__ float g_shift[GG];
__device__ unsigned int g_bar;
// tf32 hi/lo planes for 3xTF32 GEMM
__device__ __align__(128) unsigned g_Ah[(size_t)NROWS * GG];
__device__ __align__(128) unsigned g_Al[(size_t)NROWS * GG];
__device__ __align__(128) unsigned g_Wh[(size_t)GG * GG];
__device__ __align__(128) unsigned g_Wl[(size_t)GG * GG];
// interleaved U for f32x2 recurrence: [blk][k][16] = a-pairs(c0..c7), z-pairs(c0..c7)
__device__ __align__(128) float g_Up[(size_t)128 * 1024 * 16];

// ---------------- helpers ----------------
__device__ __forceinline__ void tf32split(float v, unsigned& hi, unsigned& lo)
{
    asm("cvt.rna.tf32.f32 %0, %1;" : "=r"(hi) : "f"(v));
    float l = v - __uint_as_float(hi);
    asm("cvt.rna.tf32.f32 %0, %1;" : "=r"(lo) : "f"(l));
}

__device__ __forceinline__ void cp16(unsigned int d, const void* s) {
    asm volatile("cp.async.cg.shared.global [%0], [%1], 16;" :: "r"(d), "l"(s));
}

__device__ __forceinline__ void mma_tf32(float* c, const unsigned* a, const unsigned* b)
{
    asm volatile(
        "mma.sync.aligned.m16n8k8.row.col.f32.tf32.tf32.f32 "
        "{%0,%1,%2,%3}, {%4,%5,%6,%7}, {%8,%9}, {%0,%1,%2,%3};"
        : "+f"(c[0]), "+f"(c[1]), "+f"(c[2]), "+f"(c[3])
        : "r"(a[0]), "r"(a[1]), "r"(a[2]), "r"(a[3]), "r"(b[0]), "r"(b[1]));
}

__device__ __forceinline__ ull fma2(ull a, ull b, ull c)
{
    ull d;
    asm("fma.rn.f32x2 %0, %1, %2, %3;" : "=l"(d) : "l"(a), "l"(b), "l"(c));
    return d;
}
__device__ __forceinline__ ull pack2(float lo, float hi)
{
    ull d;
    asm("mov.b64 %0, {%1, %2};" : "=l"(d) : "f"(lo), "f"(hi));
    return d;
}

// ---------------- prep: gather A (bidir concat) + tf32 split ----------------
__global__ __launch_bounds__(256) void convA_kernel(const float* __restrict__ X,
                                                    int F, int layer)
{
    int r  = blockIdx.x;
    int b2 = r / TT;
    int t  = r - b2 * TT;
    int b  = b2 & 15;
    int tt = (b2 < BB) ? t : (TT - 1 - t);
    const float* srcF;
    const float* srcB;
    if (layer == 0) {
        srcF = X + (size_t)(b * TT + tt) * 512;
        srcB = srcF;
    } else {
        srcF = g_hs0 + (size_t)(b * TT + tt) * HH;
        srcB = g_hs0 + (size_t)((b + 16) * TT + (TT - 1 - tt)) * HH - HH; // valid for f>=HH
    }
    size_t base = (size_t)r * F;
    for (int f = threadIdx.x; f < F; f += 256) {
        float v = (layer == 0 || f < HH) ? srcF[f] : srcB[f];
        unsigned hi, lo;
        tf32split(v, hi, lo);
        g_Ah[base + f] = hi;
        g_Al[base + f] = lo;
    }
}

__global__ __launch_bounds__(256) void convW_kernel(const float* __restrict__ Wm, int n)
{
    int i = (blockIdx.x * 256 + threadIdx.x) * 4;
    if (i >= n) return;
    float4 v = *(const float4*)(Wm + i);
    unsigned h0, l0, h1, l1, h2, l2, h3, l3;
    tf32split(v.x, h0, l0);
    tf32split(v.y, h1, l1);
    tf32split(v.z, h2, l2);
    tf32split(v.w, h3, l3);
    *(uint4*)(g_Wh + i) = make_uint4(h0, h1, h2, h3);
    *(uint4*)(g_Wl + i) = make_uint4(l0, l1, l2, l3);
}

// interleave U for the f32x2 recurrence
__global__ __launch_bounds__(256) void convU_kernel(const float* __restrict__ U)
{
    int idx = blockIdx.x * 256 + threadIdx.x;     // over 128*1024*16
    int slot = idx & 15;
    int k    = (idx >> 4) & 1023;
    int blk  = idx >> 14;
    int g = (slot < 8) ? (blk * 8 + slot) : (HH + blk * 8 + (slot - 8));
    g_Up[idx] = U[(size_t)g * HH + k];
}

// ---------------- 3xTF32 GEMM (unchanged from round 9) ----------------
#define PLANE 2560
#define GEMM_SMEM (2 * 4 * PLANE * 4)

__global__ __launch_bounds__(256, 1) void gemm_tf32_kernel(int F)
{
    extern __shared__ unsigned smu[];

    const int tid  = threadIdx.x;
    const int row0 = blockIdx.y * 128;
    const int col0 = blockIdx.x * 128;
    const int w    = tid >> 5;
    const int lane = tid & 31;
    const int grp  = lane >> 2;
    const int tg   = lane & 3;
    const int wm   = w >> 2;
    const int wn   = w & 3;

    const unsigned smbase = (unsigned)__cvta_generic_to_shared(smu);
    const int nt = F / 16;

    float c[4][4][4];
#pragma unroll
    for (int i = 0; i < 4; i++)
#pragma unroll
        for (int j = 0; j < 4; j++)
#pragma unroll
            for (int q = 0; q < 4; q++) c[i][j][q] = 0.f;

#define LOAD_TILE(IT, BUF)                                                           \
    do {                                                                             \
        int kk = (IT) * 16;                                                          \
        unsigned sb = smbase + (BUF) * 4 * PLANE * 4;                                \
        _Pragma("unroll")                                                            \
        for (int p = 0; p < 4; p++) {                                                \
            const unsigned* src = (p == 0) ? g_Ah : (p == 1) ? g_Al                  \
                                  : (p == 2) ? g_Wh : g_Wl;                          \
            size_t gb = (p < 2) ? ((size_t)row0 * F) : ((size_t)col0 * F);           \
            _Pragma("unroll")                                                        \
            for (int rep = 0; rep < 2; rep++) {                                      \
                int idx = rep * 256 + tid;                                           \
                int row = idx >> 2, ch = idx & 3;                                    \
                cp16(sb + p * PLANE * 4 + row * 80 + ch * 16,                        \
                     src + gb + (size_t)row * F + kk + ch * 4);                      \
            }                                                                        \
        }                                                                            \
        asm volatile("cp.async.commit_group;");                                      \
    } while (0)

    LOAD_TILE(0, 0);

    for (int it = 0; it < nt; it++) {
        if (it + 1 < nt) {
            LOAD_TILE(it + 1, (it + 1) & 1);
            asm volatile("cp.async.wait_group 1;");
        } else {
            asm volatile("cp.async.wait_group 0;");
        }
        __syncthreads();

        const unsigned* SA  = smu + (it & 1) * 4 * PLANE;
        const unsigned* SAl = SA + PLANE;
        const unsigned* SBh = SA + 2 * PLANE;
        const unsigned* SBl = SA + 3 * PLANE;

#pragma unroll
        for (int k0 = 0; k0 < 16; k0 += 8) {
            unsigned ah[4][4], al[4][4], bh[4][2], bl[4][2];
#pragma unroll
            for (int mi = 0; mi < 4; mi++) {
                int m = wm * 64 + mi * 16;
                ah[mi][0] = SA [(m + grp)     * 20 + k0 + tg];
                ah[mi][1] = SA [(m + 8 + grp) * 20 + k0 + tg];
                ah[mi][2] = SA [(m + grp)     * 20 + k0 + tg + 4];
                ah[mi][3] = SA [(m + 8 + grp) * 20 + k0 + tg + 4];
                al[mi][0] = SAl[(m + grp)     * 20 + k0 + tg];
                al[mi][1] = SAl[(m + 8 + grp) * 20 + k0 + tg];
                al[mi][2] = SAl[(m + grp)     * 20 + k0 + tg + 4];
                al[mi][3] = SAl[(m + 8 + grp) * 20 + k0 + tg + 4];
            }
#pragma unroll
            for (int ni = 0; ni < 4; ni++) {
                int n = wn * 32 + ni * 8;
                bh[ni][0] = SBh[(n + grp) * 20 + k0 + tg];
                bh[ni][1] = SBh[(n + grp) * 20 + k0 + tg + 4];
                bl[ni][0] = SBl[(n + grp) * 20 + k0 + tg];
                bl[ni][1] = SBl[(n + grp) * 20 + k0 + tg + 4];
            }
#pragma unroll
            for (int mi = 0; mi < 4; mi++)
#pragma unroll
                for (int ni = 0; ni < 4; ni++) {
                    mma_tf32(c[mi][ni], ah[mi], bh[ni]);
                    mma_tf32(c[mi][ni], ah[mi], bl[ni]);
                    mma_tf32(c[mi][ni], al[mi], bh[ni]);
                }
        }
        __syncthreads();
    }

#pragma unroll
    for (int mi = 0; mi < 4; mi++)
#pragma unroll
        for (int ni = 0; ni < 4; ni++) {
            int r   = row0 + wm * 64 + mi * 16 + grp;
            int cix = col0 + wn * 32 + ni * 8 + tg * 2;
            *(float2*)(g_w + (size_t)r * GG + cix)       = make_float2(c[mi][ni][0], c[mi][ni][1]);
            *(float2*)(g_w + (size_t)(r + 8) * GG + cix) = make_float2(c[mi][ni][2], c[mi][ni][3]);
        }
#undef LOAD_TILE
}

// ---------------- batch-norm stats (deterministic two-stage) ----------------
__global__ void stats_partial_kernel()
{
    int col = blockIdx.x * 256 + threadIdx.x;
    int r0  = blockIdx.y * 128;
    float s = 0.f, q = 0.f;
    for (int i = 0; i < 128; i++) {
        float v = g_w[(size_t)(r0 + i) * GG + col];
        s += v;
        q += v * v;
    }
    g_psum[blockIdx.y * GG + col] = s;
    g_psq [blockIdx.y * GG + col] = q;
}

__global__ void stats_final_kernel(const float* __restrict__ gamma,
                                   const float* __restrict__ beta)
{
    int col = blockIdx.x * 256 + threadIdx.x;
    float s = 0.f, q = 0.f;
    for (int i = 0; i < 125; i++) {
        s += g_psum[i * GG + col];
        q += g_psq [i * GG + col];
    }
    float mean = s * (1.f / 16000.f);
    float var  = q * (1.f / 16000.f) - mean * mean;
    float sc   = gamma[col] * rsqrtf(var + 1e-5f);
    g_scale[col] = sc;
    g_shift[col] = beta[col] - mean * sc;
}

// ---------------- normalize + transpose: g_wT[t][g][b2] ----------------
__global__ __launch_bounds__(256) void normT_kernel()
{
    __shared__ float tile[32][33];
    int g0  = blockIdx.x * 32;
    int t   = blockIdx.y;
    int tid = threadIdx.x;
    {
        int b2 = tid >> 3, gq = (tid & 7) * 4;
        float4 v = *(const float4*)(g_w + (size_t)(b2 * TT + t) * GG + g0 + gq);
        tile[b2][gq + 0] = v.x; tile[b2][gq + 1] = v.y;
        tile[b2][gq + 2] = v.z; tile[b2][gq + 3] = v.w;
    }
    __syncthreads();
    {
        int gr = tid >> 3, bq = (tid & 7) * 4;
        float sc = g_scale[g0 + gr], sh = g_shift[g0 + gr];
        float4 o;
        o.x = tile[bq + 0][gr] * sc + sh;
        o.y = tile[bq + 1][gr] * sc + sh;
        o.z = tile[bq + 2][gr] * sc + sh;
        o.w = tile[bq + 3][gr] * sc + sh;
        *(float4*)(g_wT + ((size_t)t * GG + g0 + gr) * B2 + bq) = o;
    }
}

__global__ void reset_bar_kernel() { g_bar = 0u; }

// ---------------- persistent recurrence v3 ----------------
// 128 blocks (1/SM), 256 threads = 8 warps. Block owns h-columns blk*8..+7
// (gates a: same idx, z: +1024). Warp w owns k-slice [w*128, w*128+128) and
// computes f32x2 partials for ALL 8 column-pairs; h read straight from L2
// via __ldcg (each element touched by exactly one warp). Partials exchanged
// through smem (u64); warp w then finalizes column c=w (gates, h update).
#define REC_SMEM ((16384 + 4096 + 256) * 4)   // Us(64K) + Pa(16K) + So(1K)

__device__ __forceinline__ void grid_barrier(unsigned int phase)
{
    __syncthreads();
    if (threadIdx.x == 0) {
        __threadfence();
        atomicAdd(&g_bar, 1u);
        unsigned int target = phase * gridDim.x;
        while (*((volatile unsigned int*)&g_bar) < target) { }
        __threadfence();
    }
    __syncthreads();
}

__global__ __launch_bounds__(256, 1) void recur_kernel(float* __restrict__ out,
                                                       int layer)
{
    extern __shared__ float sm[];
    float* Us  = sm;                       // 16384 floats: [k][16] interleaved U
    ull*   Pau = (ull*)(sm + 16384);       // 2048 u64 partials [srcwarp][8][lane]
    float* Paf = sm + 16384;               // float view
    float* So  = sm + 16384 + 4096;        // 256 floats out staging [b][8]

    const int tid  = threadIdx.x;
    const int blk  = blockIdx.x;
    const int w    = tid >> 5;
    const int lane = tid & 31;
    const int k0   = w * 128;              // this warp's k-slice

    // load interleaved U slice (64 KB contiguous, coalesced)
    {
        const float4* src = (const float4*)(g_Up + (size_t)blk * 1024 * 16);
        float4* dst = (float4*)Us;
        for (int e = tid; e < 4096; e += 256) dst[e] = src[e];
    }

    // zero h parity 0 (128*256 = HS exactly)
    g_h[blk * 256 + tid] = 0.f;

    grid_barrier(1);

    const int c   = w;                      // finalized column for this warp
    const int gac = blk * 8 + c;
    const int jc  = c >> 1, hc = c & 1;
    float hp = 0.f;                         // h_prev for (column c, batch lane)

    for (int t = 0; t < TT; t++) {
        const int cur = t & 1;
        const int nxt = cur ^ 1;

        // input-projection contributions for the finalized column (early issue)
        const float* wt = g_wT + (size_t)t * GG * B2;
        float a_sum = wt[gac * 32 + lane];
        float z_sum = wt[(HH + gac) * 32 + lane];

        // f32x2 partial GEMV over this warp's k-slice
        ull acc0 = 0, acc1 = 0, acc2 = 0, acc3 = 0;
        ull acc4 = 0, acc5 = 0, acc6 = 0, acc7 = 0;
        {
            const float* hb = g_h + cur * HS + k0 * 32 + lane;
            const ulonglong2* Urow = (const ulonglong2*)(Us) + k0 * 4;
#pragma unroll 4
            for (int k = 0; k < 128; k++) {
                float h = __ldcg(hb + k * 32);
                ull hh = pack2(h, h);
                ulonglong2 p0 = Urow[k * 4 + 0];
                ulonglong2 p1 = Urow[k * 4 + 1];
                ulonglong2 p2 = Urow[k * 4 + 2];
                ulonglong2 p3 = Urow[k * 4 + 3];
                acc0 = fma2(p0.x, hh, acc0);
                acc1 = fma2(p0.y, hh, acc1);
                acc2 = fma2(p1.x, hh, acc2);
                acc3 = fma2(p1.y, hh, acc3);
                acc4 = fma2(p2.x, hh, acc4);
                acc5 = fma2(p2.y, hh, acc5);
                acc6 = fma2(p3.x, hh, acc6);
                acc7 = fma2(p3.y, hh, acc7);
            }
        }

        // exchange partials
        Pau[(w * 8 + 0) * 32 + lane] = acc0;
        Pau[(w * 8 + 1) * 32 + lane] = acc1;
        Pau[(w * 8 + 2) * 32 + lane] = acc2;
        Pau[(w * 8 + 3) * 32 + lane] = acc3;
        Pau[(w * 8 + 4) * 32 + lane] = acc4;
        Pau[(w * 8 + 5) * 32 + lane] = acc5;
        Pau[(w * 8 + 6) * 32 + lane] = acc6;
        Pau[(w * 8 + 7) * 32 + lane] = acc7;
        __syncthreads();

        // finalize column c = w
#pragma unroll
        for (int s = 0; s < 8; s++) {
            a_sum += Paf[((s * 8 + jc) * 32 + lane) * 2 + hc];
            z_sum += Paf[((s * 8 + 4 + jc) * 32 + lane) * 2 + hc];
        }
        float z  = 1.f / (1.f + expf(-z_sum));
        float hn = z * hp + (1.f - z) * fmaxf(a_sum, 0.f);
        hp = hn;
        g_h[nxt * HS + gac * 32 + lane] = hn;
        So[lane * 8 + c] = hn;
        __syncthreads();

        // coalesced sequence-output write
        {
            int b = tid >> 3, kk = tid & 7;
            float v = So[b * 8 + kk];
            if (layer == 0) {
                g_hs0[(size_t)(b * TT + t) * HH + blk * 8 + kk] = v;
            } else {
                if (b < BB)
                    out[(size_t)(b * TT + t) * GG + blk * 8 + kk] = v;
                else
                    out[(size_t)((b - BB) * TT + (TT - 1 - t)) * GG + HH + blk * 8 + kk] = v;
            }
        }

        grid_barrier((unsigned int)t + 2u);
    }
}

// ---------------- launch ----------------
extern "C" void kernel_launch(void* const* d_in, const int* in_sizes, int n_in,
                              void* d_out, int out_size)
{
    const float* x  = (const float*)d_in[0];
    const float* w0 = (const float*)d_in[1];
    const float* u0 = (const float*)d_in[2];
    const float* g0 = (const float*)d_in[3];
    const float* b0 = (const float*)d_in[4];
    const float* w1 = (const float*)d_in[5];
    const float* u1 = (const float*)d_in[6];
    const float* g1 = (const float*)d_in[7];
    const float* b1 = (const float*)d_in[8];
    float* out = (float*)d_out;

    cudaFuncSetAttribute(recur_kernel, cudaFuncAttributeMaxDynamicSharedMemorySize, REC_SMEM);
    cudaFuncSetAttribute(gemm_tf32_kernel, cudaFuncAttributeMaxDynamicSharedMemorySize, GEMM_SMEM);

    dim3 ggrid(GG / 128, NROWS / 128);   // (16, 125)
    dim3 sgrid(GG / 256, 125);           // (8, 125)
    dim3 tgrid(GG / 32, TT);             // (64, 500)

    // ---- layer 0 ----
    convA_kernel<<<NROWS, 256>>>(x, 512, 0);
    convW_kernel<<<(GG * 512) / 1024, 256>>>(w0, GG * 512);
    convU_kernel<<<(128 * 1024 * 16) / 256, 256>>>(u0);
    gemm_tf32_kernel<<<ggrid, 256, GEMM_SMEM>>>(512);
    stats_partial_kernel<<<sgrid, 256>>>();
    stats_final_kernel<<<GG / 256, 256>>>(g0, b0);
    normT_kernel<<<tgrid, 256>>>();
    reset_bar_kernel<<<1, 1>>>();
    recur_kernel<<<128, 256, REC_SMEM>>>(out, 0);

    // ---- layer 1 ----
    convA_kernel<<<NROWS, 256>>>(x, 2048, 1);
    convW_kernel<<<(GG * GG) / 1024, 256>>>(w1, GG * GG);
    convU_kernel<<<(128 * 1024 * 16) / 256, 256>>>(u1);
    gemm_tf32_kernel<<<ggrid, 256, GEMM_SMEM>>>(2048);
    stats_partial_kernel<<<sgrid, 256>>>();
    stats_final_kernel<<<GG / 256, 256>>>(g1, b1);
    normT_kernel<<<tgrid, 256>>>();
    reset_bar_kernel<<<1, 1>>>();
    recur_kernel<<<128, 256, REC_SMEM>>>(u1 ? out : out, 1);
}

// round 12
// speedup vs baseline: 1.3772x; 1.3772x over previous
#include <cuda_runtime.h>
#include <math.h>
#include <stdint.h>

// Problem constants
#define BB    16
#define B2    32
#define TT    500
#define HH    1024
#define GG    2048
#define NROWS 16000
#define HS    (HH * B2)

typedef unsigned long long ull;

// ---------------- scratch (device globals; no allocation) ----------------
__device__ __align__(128) float g_w  [(size_t)NROWS * GG];   // raw input projections [r][g]
__device__ __align__(128) float g_wT [(size_t)TT * GG * B2]; // normalized, [t][g][b2]
__device__ __align__(128) float g_hs0[(size_t)B2 * TT * HH]; // layer-0 hidden sequence
__device__ __align__(128) float g_h  [2 * HS];               // double-buffered h, [parity][k][b]
__device__ __align__(128) float g_psum[125 * GG];
__device__ __align__(128) float g_psq [125 * GG];
__device__ float g_scale[GG];
__device__ float g_shift[GG];
__device__ unsigned int g_bar;
// tf32 hi/lo planes for 3xTF32 GEMM
__device__ __align__(128) unsigned g_Ah[(size_t)NROWS * GG];
__device__ __align__(128) unsigned g_Al[(size_t)NROWS * GG];
__device__ __align__(128) unsigned g_Wh[(size_t)GG * GG];
__device__ __align__(128) unsigned g_Wl[(size_t)GG * GG];
// interleaved U for f32x2 recurrence: [blk][k][16] = a-pairs(c0..c7), z-pairs(c0..c7)
__device__ __align__(128) float g_Up[(size_t)128 * 1024 * 16];

// ---------------- helpers ----------------
__device__ __forceinline__ void tf32split(float v, unsigned& hi, unsigned& lo)
{
    asm("cvt.rna.tf32.f32 %0, %1;" : "=r"(hi) : "f"(v));
    float l = v - __uint_as_float(hi);
    asm("cvt.rna.tf32.f32 %0, %1;" : "=r"(lo) : "f"(l));
}

__device__ __forceinline__ void cp16(unsigned int d, const void* s) {
    asm volatile("cp.async.cg.shared.global [%0], [%1], 16;" :: "r"(d), "l"(s));
}

__device__ __forceinline__ void mma_tf32(float* c, const unsigned* a, const unsigned* b)
{
    asm volatile(
        "mma.sync.aligned.m16n8k8.row.col.f32.tf32.tf32.f32 "
        "{%0,%1,%2,%3}, {%4,%5,%6,%7}, {%8,%9}, {%0,%1,%2,%3};"
        : "+f"(c[0]), "+f"(c[1]), "+f"(c[2]), "+f"(c[3])
        : "r"(a[0]), "r"(a[1]), "r"(a[2]), "r"(a[3]), "r"(b[0]), "r"(b[1]));
}

__device__ __forceinline__ ull fma2(ull a, ull b, ull c)
{
    ull d;
    asm("fma.rn.f32x2 %0, %1, %2, %3;" : "=l"(d) : "l"(a), "l"(b), "l"(c));
    return d;
}
__device__ __forceinline__ ull pack2(float lo, float hi)
{
    ull d;
    asm("mov.b64 %0, {%1, %2};" : "=l"(d) : "f"(lo), "f"(hi));
    return d;
}

// ---------------- prep: gather A (bidir concat) + tf32 split ----------------
__global__ __launch_bounds__(256) void convA_kernel(const float* __restrict__ X,
                                                    int F, int layer)
{
    int r  = blockIdx.x;
    int b2 = r / TT;
    int t  = r - b2 * TT;
    int b  = b2 & 15;
    int tt = (b2 < BB) ? t : (TT - 1 - t);
    const float* srcF;
    const float* srcB;
    if (layer == 0) {
        srcF = X + (size_t)(b * TT + tt) * 512;
        srcB = srcF;
    } else {
        srcF = g_hs0 + (size_t)(b * TT + tt) * HH;
        srcB = g_hs0 + (size_t)((b + 16) * TT + (TT - 1 - tt)) * HH - HH; // valid for f>=HH
    }
    size_t base = (size_t)r * F;
    for (int f = threadIdx.x; f < F; f += 256) {
        float v = (layer == 0 || f < HH) ? srcF[f] : srcB[f];
        unsigned hi, lo;
        tf32split(v, hi, lo);
        g_Ah[base + f] = hi;
        g_Al[base + f] = lo;
    }
}

__global__ __launch_bounds__(256) void convW_kernel(const float* __restrict__ Wm, int n)
{
    int i = (blockIdx.x * 256 + threadIdx.x) * 4;
    if (i >= n) return;
    float4 v = *(const float4*)(Wm + i);
    unsigned h0, l0, h1, l1, h2, l2, h3, l3;
    tf32split(v.x, h0, l0);
    tf32split(v.y, h1, l1);
    tf32split(v.z, h2, l2);
    tf32split(v.w, h3, l3);
    *(uint4*)(g_Wh + i) = make_uint4(h0, h1, h2, h3);
    *(uint4*)(g_Wl + i) = make_uint4(l0, l1, l2, l3);
}

// interleave U for the f32x2 recurrence
__global__ __launch_bounds__(256) void convU_kernel(const float* __restrict__ U)
{
    int idx = blockIdx.x * 256 + threadIdx.x;     // over 128*1024*16
    int slot = idx & 15;
    int k    = (idx >> 4) & 1023;
    int blk  = idx >> 14;
    int g = (slot < 8) ? (blk * 8 + slot) : (HH + blk * 8 + (slot - 8));
    g_Up[idx] = U[(size_t)g * HH + k];
}

// ---------------- 3xTF32 GEMM ----------------
#define PLANE 2560
#define GEMM_SMEM (2 * 4 * PLANE * 4)

__global__ __launch_bounds__(256, 1) void gemm_tf32_kernel(int F)
{
    extern __shared__ unsigned smu[];

    const int tid  = threadIdx.x;
    const int row0 = blockIdx.y * 128;
    const int col0 = blockIdx.x * 128;
    const int w    = tid >> 5;
    const int lane = tid & 31;
    const int grp  = lane >> 2;
    const int tg   = lane & 3;
    const int wm   = w >> 2;
    const int wn   = w & 3;

    const unsigned smbase = (unsigned)__cvta_generic_to_shared(smu);
    const int nt = F / 16;

    float c[4][4][4];
#pragma unroll
    for (int i = 0; i < 4; i++)
#pragma unroll
        for (int j = 0; j < 4; j++)
#pragma unroll
            for (int q = 0; q < 4; q++) c[i][j][q] = 0.f;

#define LOAD_TILE(IT, BUF)                                                           \
    do {                                                                             \
        int kk = (IT) * 16;                                                          \
        unsigned sb = smbase + (BUF) * 4 * PLANE * 4;                                \
        _Pragma("unroll")                                                            \
        for (int p = 0; p < 4; p++) {                                                \
            const unsigned* src = (p == 0) ? g_Ah : (p == 1) ? g_Al                  \
                                  : (p == 2) ? g_Wh : g_Wl;                          \
            size_t gb = (p < 2) ? ((size_t)row0 * F) : ((size_t)col0 * F);           \
            _Pragma("unroll")                                                        \
            for (int rep = 0; rep < 2; rep++) {                                      \
                int idx = rep * 256 + tid;                                           \
                int row = idx >> 2, ch = idx & 3;                                    \
                cp16(sb + p * PLANE * 4 + row * 80 + ch * 16,                        \
                     src + gb + (size_t)row * F + kk + ch * 4);                      \
            }                                                                        \
        }                                                                            \
        asm volatile("cp.async.commit_group;");                                      \
    } while (0)

    LOAD_TILE(0, 0);

    for (int it = 0; it < nt; it++) {
        if (it + 1 < nt) {
            LOAD_TILE(it + 1, (it + 1) & 1);
            asm volatile("cp.async.wait_group 1;");
        } else {
            asm volatile("cp.async.wait_group 0;");
        }
        __syncthreads();

        const unsigned* SA  = smu + (it & 1) * 4 * PLANE;
        const unsigned* SAl = SA + PLANE;
        const unsigned* SBh = SA + 2 * PLANE;
        const unsigned* SBl = SA + 3 * PLANE;

#pragma unroll
        for (int k0 = 0; k0 < 16; k0 += 8) {
            unsigned ah[4][4], al[4][4], bh[4][2], bl[4][2];
#pragma unroll
            for (int mi = 0; mi < 4; mi++) {
                int m = wm * 64 + mi * 16;
                ah[mi][0] = SA [(m + grp)     * 20 + k0 + tg];
                ah[mi][1] = SA [(m + 8 + grp) * 20 + k0 + tg];
                ah[mi][2] = SA [(m + grp)     * 20 + k0 + tg + 4];
                ah[mi][3] = SA [(m + 8 + grp) * 20 + k0 + tg + 4];
                al[mi][0] = SAl[(m + grp)     * 20 + k0 + tg];
                al[mi][1] = SAl[(m + 8 + grp) * 20 + k0 + tg];
                al[mi][2] = SAl[(m + grp)     * 20 + k0 + tg + 4];
                al[mi][3] = SAl[(m + 8 + grp) * 20 + k0 + tg + 4];
            }
#pragma unroll
            for (int ni = 0; ni < 4; ni++) {
                int n = wn * 32 + ni * 8;
                bh[ni][0] = SBh[(n + grp) * 20 + k0 + tg];
                bh[ni][1] = SBh[(n + grp) * 20 + k0 + tg + 4];
                bl[ni][0] = SBl[(n + grp) * 20 + k0 + tg];
                bl[ni][1] = SBl[(n + grp) * 20 + k0 + tg + 4];
            }
#pragma unroll
            for (int mi = 0; mi < 4; mi++)
#pragma unroll
                for (int ni = 0; ni < 4; ni++) {
                    mma_tf32(c[mi][ni], ah[mi], bh[ni]);
                    mma_tf32(c[mi][ni], ah[mi], bl[ni]);
                    mma_tf32(c[mi][ni], al[mi], bh[ni]);
                }
        }
        __syncthreads();
    }

#pragma unroll
    for (int mi = 0; mi < 4; mi++)
#pragma unroll
        for (int ni = 0; ni < 4; ni++) {
            int r   = row0 + wm * 64 + mi * 16 + grp;
            int cix = col0 + wn * 32 + ni * 8 + tg * 2;
            *(float2*)(g_w + (size_t)r * GG + cix)       = make_float2(c[mi][ni][0], c[mi][ni][1]);
            *(float2*)(g_w + (size_t)(r + 8) * GG + cix) = make_float2(c[mi][ni][2], c[mi][ni][3]);
        }
#undef LOAD_TILE
}

// ---------------- batch-norm stats (deterministic two-stage) ----------------
__global__ void stats_partial_kernel()
{
    int col = blockIdx.x * 256 + threadIdx.x;
    int r0  = blockIdx.y * 128;
    float s = 0.f, q = 0.f;
    for (int i = 0; i < 128; i++) {
        float v = g_w[(size_t)(r0 + i) * GG + col];
        s += v;
        q += v * v;
    }
    g_psum[blockIdx.y * GG + col] = s;
    g_psq [blockIdx.y * GG + col] = q;
}

__global__ void stats_final_kernel(const float* __restrict__ gamma,
                                   const float* __restrict__ beta)
{
    int col = blockIdx.x * 256 + threadIdx.x;
    float s = 0.f, q = 0.f;
    for (int i = 0; i < 125; i++) {
        s += g_psum[i * GG + col];
        q += g_psq [i * GG + col];
    }
    float mean = s * (1.f / 16000.f);
    float var  = q * (1.f / 16000.f) - mean * mean;
    float sc   = gamma[col] * rsqrtf(var + 1e-5f);
    g_scale[col] = sc;
    g_shift[col] = beta[col] - mean * sc;
}

// ---------------- normalize + transpose: g_wT[t][g][b2] ----------------
__global__ __launch_bounds__(256) void normT_kernel()
{
    __shared__ float tile[32][33];
    int g0  = blockIdx.x * 32;
    int t   = blockIdx.y;
    int tid = threadIdx.x;
    {
        int b2 = tid >> 3, gq = (tid & 7) * 4;
        float4 v = *(const float4*)(g_w + (size_t)(b2 * TT + t) * GG + g0 + gq);
        tile[b2][gq + 0] = v.x; tile[b2][gq + 1] = v.y;
        tile[b2][gq + 2] = v.z; tile[b2][gq + 3] = v.w;
    }
    __syncthreads();
    {
        int gr = tid >> 3, bq = (tid & 7) * 4;
        float sc = g_scale[g0 + gr], sh = g_shift[g0 + gr];
        float4 o;
        o.x = tile[bq + 0][gr] * sc + sh;
        o.y = tile[bq + 1][gr] * sc + sh;
        o.z = tile[bq + 2][gr] * sc + sh;
        o.w = tile[bq + 3][gr] * sc + sh;
        *(float4*)(g_wT + ((size_t)t * GG + g0 + gr) * B2 + bq) = o;
    }
}

__global__ void reset_bar_kernel() { g_bar = 0u; }

// ---------------- persistent recurrence v4 ----------------
// 128 blocks (1/SM), 256 threads = 8 warps. Block owns h-columns blk*8..+7.
// Warp w owns k-slice [w*128, w*128+128): it cp.asyncs ITS OWN 16 KB h slice
// into smem (2 committed halves, per-warp wait, no cross-warp sync), then
// computes f32x2 partials for all 8 column-pairs against interleaved U in
// smem. One __syncthreads for the u64 partial exchange; warp w finalizes
// column c=w (gates + h update).
#define REC_SMEM ((16384 + HS + 4096 + 256) * 4)   // 214 KB

__device__ __forceinline__ void grid_barrier(unsigned int phase)
{
    __syncthreads();
    if (threadIdx.x == 0) {
        __threadfence();
        atomicAdd(&g_bar, 1u);
        unsigned int target = phase * gridDim.x;
        while (*((volatile unsigned int*)&g_bar) < target) { __nanosleep(32); }
        __threadfence();
    }
    __syncthreads();
}

__global__ __launch_bounds__(256, 1) void recur_kernel(float* __restrict__ out,
                                                       int layer)
{
    extern __shared__ float sm[];
    float* Us  = sm;                         // 16384 floats: [k][16] interleaved U
    float* Hs  = sm + 16384;                 // 32768 floats: staged h [k][b]
    ull*   Pau = (ull*)(sm + 16384 + HS);    // 2048 u64 partials
    float* Paf = sm + 16384 + HS;            // float view
    float* So  = sm + 16384 + HS + 4096;     // 256 floats out staging [b][8]

    const int tid  = threadIdx.x;
    const int blk  = blockIdx.x;
    const int w    = tid >> 5;
    const int lane = tid & 31;
    const int k0   = w * 128;                // this warp's k-slice

    // load interleaved U slice (64 KB contiguous, coalesced)
    {
        const float4* src = (const float4*)(g_Up + (size_t)blk * 1024 * 16);
        float4* dst = (float4*)Us;
        for (int e = tid; e < 4096; e += 256) dst[e] = src[e];
    }

    // zero h parity 0 (128*256 = HS exactly)
    g_h[blk * 256 + tid] = 0.f;

    grid_barrier(1);

    const int c   = w;                       // finalized column for this warp
    const int gac = blk * 8 + c;
    const int jc  = c >> 1, hc = c & 1;
    float hp = 0.f;

    const unsigned hs_base = (unsigned)__cvta_generic_to_shared(Hs);
    const ulonglong2* Urow = (const ulonglong2*)Us;

    for (int t = 0; t < TT; t++) {
        const int cur = t & 1;
        const int nxt = cur ^ 1;

        // stage this warp's own h slice: 1024 float4s, two halves of 512
        const float* hsrc = g_h + cur * HS;
#pragma unroll
        for (int half = 0; half < 2; half++) {
#pragma unroll
            for (int i = 0; i < 16; i++) {
                int j = k0 * 8 + half * 512 + i * 32 + lane;  // float4 index
                cp16(hs_base + j * 16, hsrc + j * 4);
            }
            asm volatile("cp.async.commit_group;");
        }

        // input-projection contributions for the finalized column
        const float* wt = g_wT + (size_t)t * GG * B2;
        float a_sum = wt[gac * 32 + lane];
        float z_sum = wt[(HH + gac) * 32 + lane];

        ull acc0 = 0, acc1 = 0, acc2 = 0, acc3 = 0;
        ull acc4 = 0, acc5 = 0, acc6 = 0, acc7 = 0;

        asm volatile("cp.async.wait_group 1;");
#pragma unroll 4
        for (int k = k0; k < k0 + 64; k++) {
            float h = Hs[k * 32 + lane];
            ull hh = pack2(h, h);
            ulonglong2 p0 = Urow[k * 4 + 0];
            ulonglong2 p1 = Urow[k * 4 + 1];
            ulonglong2 p2 = Urow[k * 4 + 2];
            ulonglong2 p3 = Urow[k * 4 + 3];
            acc0 = fma2(p0.x, hh, acc0);
            acc1 = fma2(p0.y, hh, acc1);
            acc2 = fma2(p1.x, hh, acc2);
            acc3 = fma2(p1.y, hh, acc3);
            acc4 = fma2(p2.x, hh, acc4);
            acc5 = fma2(p2.y, hh, acc5);
            acc6 = fma2(p3.x, hh, acc6);
            acc7 = fma2(p3.y, hh, acc7);
        }
        asm volatile("cp.async.wait_group 0;");
#pragma unroll 4
        for (int k = k0 + 64; k < k0 + 128; k++) {
            float h = Hs[k * 32 + lane];
            ull hh = pack2(h, h);
            ulonglong2 p0 = Urow[k * 4 + 0];
            ulonglong2 p1 = Urow[k * 4 + 1];
            ulonglong2 p2 = Urow[k * 4 + 2];
            ulonglong2 p3 = Urow[k * 4 + 3];
            acc0 = fma2(p0.x, hh, acc0);
            acc1 = fma2(p0.y, hh, acc1);
            acc2 = fma2(p1.x, hh, acc2);
            acc3 = fma2(p1.y, hh, acc3);
            acc4 = fma2(p2.x, hh, acc4);
            acc5 = fma2(p2.y, hh, acc5);
            acc6 = fma2(p3.x, hh, acc6);
            acc7 = fma2(p3.y, hh, acc7);
        }

        // exchange partials
        Pau[(w * 8 + 0) * 32 + lane] = acc0;
        Pau[(w * 8 + 1) * 32 + lane] = acc1;
        Pau[(w * 8 + 2) * 32 + lane] = acc2;
        Pau[(w * 8 + 3) * 32 + lane] = acc3;
        Pau[(w * 8 + 4) * 32 + lane] = acc4;
        Pau[(w * 8 + 5) * 32 + lane] = acc5;
        Pau[(w * 8 + 6) * 32 + lane] = acc6;
        Pau[(w * 8 + 7) * 32 + lane] = acc7;
        __syncthreads();

        // finalize column c = w
#pragma unroll
        for (int s = 0; s < 8; s++) {
            a_sum += Paf[((s * 8 + jc) * 32 + lane) * 2 + hc];
            z_sum += Paf[((s * 8 + 4 + jc) * 32 + lane) * 2 + hc];
        }
        float z  = 1.f / (1.f + expf(-z_sum));
        float hn = z * hp + (1.f - z) * fmaxf(a_sum, 0.f);
        hp = hn;
        g_h[nxt * HS + gac * 32 + lane] = hn;
        So[lane * 8 + c] = hn;
        __syncthreads();

        // coalesced sequence-output write
        {
            int b = tid >> 3, kk = tid & 7;
            float v = So[b * 8 + kk];
            if (layer == 0) {
                g_hs0[(size_t)(b * TT + t) * HH + blk * 8 + kk] = v;
            } else {
                if (b < BB)
                    out[(size_t)(b * TT + t) * GG + blk * 8 + kk] = v;
                else
                    out[(size_t)((b - BB) * TT + (TT - 1 - t)) * GG + HH + blk * 8 + kk] = v;
            }
        }

        grid_barrier((unsigned int)t + 2u);
    }
}

// ---------------- launch ----------------
extern "C" void kernel_launch(void* const* d_in, const int* in_sizes, int n_in,
                              void* d_out, int out_size)
{
    const float* x  = (const float*)d_in[0];
    const float* w0 = (const float*)d_in[1];
    const float* u0 = (const float*)d_in[2];
    const float* g0 = (const float*)d_in[3];
    const float* b0 = (const float*)d_in[4];
    const float* w1 = (const float*)d_in[5];
    const float* u1 = (const float*)d_in[6];
    const float* g1 = (const float*)d_in[7];
    const float* b1 = (const float*)d_in[8];
    float* out = (float*)d_out;

    cudaFuncSetAttribute(recur_kernel, cudaFuncAttributeMaxDynamicSharedMemorySize, REC_SMEM);
    cudaFuncSetAttribute(gemm_tf32_kernel, cudaFuncAttributeMaxDynamicSharedMemorySize, GEMM_SMEM);

    dim3 ggrid(GG / 128, NROWS / 128);   // (16, 125)
    dim3 sgrid(GG / 256, 125);           // (8, 125)
    dim3 tgrid(GG / 32, TT);             // (64, 500)

    // ---- layer 0 ----
    convA_kernel<<<NROWS, 256>>>(x, 512, 0);
    convW_kernel<<<(GG * 512) / 1024, 256>>>(w0, GG * 512);
    convU_kernel<<<(128 * 1024 * 16) / 256, 256>>>(u0);
    gemm_tf32_kernel<<<ggrid, 256, GEMM_SMEM>>>(512);
    stats_partial_kernel<<<sgrid, 256>>>();
    stats_final_kernel<<<GG / 256, 256>>>(g0, b0);
    normT_kernel<<<tgrid, 256>>>();
    reset_bar_kernel<<<1, 1>>>();
    recur_kernel<<<128, 256, REC_SMEM>>>(out, 0);

    // ---- layer 1 ----
    convA_kernel<<<NROWS, 256>>>(x, 2048, 1);
    convW_kernel<<<(GG * GG) / 1024, 256>>>(w1, GG * GG);
    convU_kernel<<<(128 * 1024 * 16) / 256, 256>>>(u1);
    gemm_tf32_kernel<<<ggrid, 256, GEMM_SMEM>>>(2048);
    stats_partial_kernel<<<sgrid, 256>>>();
    stats_final_kernel<<<GG / 256, 256>>>(g1, b1);
    normT_kernel<<<tgrid, 256>>>();
    reset_bar_kernel<<<1, 1>>>();
    recur_kernel<<<128, 256, REC_SMEM>>>(out, 1);
}

// round 13
// speedup vs baseline: 1.5781x; 1.1459x over previous
#include <cuda_runtime.h>
#include <math.h>
#include <stdint.h>

// Problem constants
#define BB    16
#define B2    32
#define TT    500
#define HH    1024
#define GG    2048
#define NROWS 16000
#define HS    (HH * B2)

typedef unsigned long long ull;

// ---------------- scratch (device globals; no allocation) ----------------
__device__ __align__(128) float g_w  [(size_t)NROWS * GG];   // raw input projections [r][g]
__device__ __align__(128) float g_wT [(size_t)TT * GG * B2]; // normalized, [t][g][b2]
__device__ __align__(128) float g_hs0[(size_t)B2 * TT * HH]; // layer-0 hidden sequence
__device__ __align__(128) float g_h  [2 * HS];               // double-buffered h, [parity][k][b]
__device__ __align__(128) float g_psum[125 * GG];
__device__ __align__(128) float g_psq [125 * GG];
__device__ float g_scale[GG];
__device__ float g_shift[GG];
__device__ unsigned int g_bar;
// tf32 hi/lo planes for 3xTF32 GEMM
__device__ __align__(128) unsigned g_Ah[(size_t)NROWS * GG];
__device__ __align__(128) unsigned g_Al[(size_t)NROWS * GG];
__device__ __align__(128) unsigned g_Wh[(size_t)GG * GG];
__device__ __align__(128) unsigned g_Wl[(size_t)GG * GG];

// ---------------- helpers ----------------
__device__ __forceinline__ void tf32split(float v, unsigned& hi, unsigned& lo)
{
    asm("cvt.rna.tf32.f32 %0, %1;" : "=r"(hi) : "f"(v));
    float l = v - __uint_as_float(hi);
    asm("cvt.rna.tf32.f32 %0, %1;" : "=r"(lo) : "f"(l));
}

__device__ __forceinline__ void cp16(unsigned int d, const void* s) {
    asm volatile("cp.async.cg.shared.global [%0], [%1], 16;" :: "r"(d), "l"(s));
}

__device__ __forceinline__ void mma_tf32(float* c, const unsigned* a, const unsigned* b)
{
    asm volatile(
        "mma.sync.aligned.m16n8k8.row.col.f32.tf32.tf32.f32 "
        "{%0,%1,%2,%3}, {%4,%5,%6,%7}, {%8,%9}, {%0,%1,%2,%3};"
        : "+f"(c[0]), "+f"(c[1]), "+f"(c[2]), "+f"(c[3])
        : "r"(a[0]), "r"(a[1]), "r"(a[2]), "r"(a[3]), "r"(b[0]), "r"(b[1]));
}

// ---------------- prep: gather A (bidir concat) + tf32 split ----------------
__global__ __launch_bounds__(256) void convA_kernel(const float* __restrict__ X,
                                                    int F, int layer)
{
    int r  = blockIdx.x;
    int b2 = r / TT;
    int t  = r - b2 * TT;
    int b  = b2 & 15;
    int tt = (b2 < BB) ? t : (TT - 1 - t);
    const float* srcF;
    const float* srcB;
    if (layer == 0) {
        srcF = X + (size_t)(b * TT + tt) * 512;
        srcB = srcF;
    } else {
        srcF = g_hs0 + (size_t)(b * TT + tt) * HH;
        srcB = g_hs0 + (size_t)((b + 16) * TT + (TT - 1 - tt)) * HH - HH; // valid for f>=HH
    }
    size_t base = (size_t)r * F;
    for (int f = threadIdx.x; f < F; f += 256) {
        float v = (layer == 0 || f < HH) ? srcF[f] : srcB[f];
        unsigned hi, lo;
        tf32split(v, hi, lo);
        g_Ah[base + f] = hi;
        g_Al[base + f] = lo;
    }
}

__global__ __launch_bounds__(256) void convW_kernel(const float* __restrict__ Wm, int n)
{
    int i = (blockIdx.x * 256 + threadIdx.x) * 4;
    if (i >= n) return;
    float4 v = *(const float4*)(Wm + i);
    unsigned h0, l0, h1, l1, h2, l2, h3, l3;
    tf32split(v.x, h0, l0);
    tf32split(v.y, h1, l1);
    tf32split(v.z, h2, l2);
    tf32split(v.w, h3, l3);
    *(uint4*)(g_Wh + i) = make_uint4(h0, h1, h2, h3);
    *(uint4*)(g_Wl + i) = make_uint4(l0, l1, l2, l3);
}

// ---------------- 3xTF32 GEMM (validated) ----------------
#define PLANE 2560
#define GEMM_SMEM (2 * 4 * PLANE * 4)

__global__ __launch_bounds__(256, 1) void gemm_tf32_kernel(int F)
{
    extern __shared__ unsigned smu[];

    const int tid  = threadIdx.x;
    const int row0 = blockIdx.y * 128;
    const int col0 = blockIdx.x * 128;
    const int w    = tid >> 5;
    const int lane = tid & 31;
    const int grp  = lane >> 2;
    const int tg   = lane & 3;
    const int wm   = w >> 2;
    const int wn   = w & 3;

    const unsigned smbase = (unsigned)__cvta_generic_to_shared(smu);
    const int nt = F / 16;

    float c[4][4][4];
#pragma unroll
    for (int i = 0; i < 4; i++)
#pragma unroll
        for (int j = 0; j < 4; j++)
#pragma unroll
            for (int q = 0; q < 4; q++) c[i][j][q] = 0.f;

#define LOAD_TILE(IT, BUF)                                                           \
    do {                                                                             \
        int kk = (IT) * 16;                                                          \
        unsigned sb = smbase + (BUF) * 4 * PLANE * 4;                                \
        _Pragma("unroll")                                                            \
        for (int p = 0; p < 4; p++) {                                                \
            const unsigned* src = (p == 0) ? g_Ah : (p == 1) ? g_Al                  \
                                  : (p == 2) ? g_Wh : g_Wl;                          \
            size_t gb = (p < 2) ? ((size_t)row0 * F) : ((size_t)col0 * F);           \
            _Pragma("unroll")                                                        \
            for (int rep = 0; rep < 2; rep++) {                                      \
                int idx = rep * 256 + tid;                                           \
                int row = idx >> 2, ch = idx & 3;                                    \
                cp16(sb + p * PLANE * 4 + row * 80 + ch * 16,                        \
                     src + gb + (size_t)row * F + kk + ch * 4);                      \
            }                                                                        \
        }                                                                            \
        asm volatile("cp.async.commit_group;");                                      \
    } while (0)

    LOAD_TILE(0, 0);

    for (int it = 0; it < nt; it++) {
        if (it + 1 < nt) {
            LOAD_TILE(it + 1, (it + 1) & 1);
            asm volatile("cp.async.wait_group 1;");
        } else {
            asm volatile("cp.async.wait_group 0;");
        }
        __syncthreads();

        const unsigned* SA  = smu + (it & 1) * 4 * PLANE;
        const unsigned* SAl = SA + PLANE;
        const unsigned* SBh = SA + 2 * PLANE;
        const unsigned* SBl = SA + 3 * PLANE;

#pragma unroll
        for (int k0 = 0; k0 < 16; k0 += 8) {
            unsigned ah[4][4], al[4][4], bh[4][2], bl[4][2];
#pragma unroll
            for (int mi = 0; mi < 4; mi++) {
                int m = wm * 64 + mi * 16;
                ah[mi][0] = SA [(m + grp)     * 20 + k0 + tg];
                ah[mi][1] = SA [(m + 8 + grp) * 20 + k0 + tg];
                ah[mi][2] = SA [(m + grp)     * 20 + k0 + tg + 4];
                ah[mi][3] = SA [(m + 8 + grp) * 20 + k0 + tg + 4];
                al[mi][0] = SAl[(m + grp)     * 20 + k0 + tg];
                al[mi][1] = SAl[(m + 8 + grp) * 20 + k0 + tg];
                al[mi][2] = SAl[(m + grp)     * 20 + k0 + tg + 4];
                al[mi][3] = SAl[(m + 8 + grp) * 20 + k0 + tg + 4];
            }
#pragma unroll
            for (int ni = 0; ni < 4; ni++) {
                int n = wn * 32 + ni * 8;
                bh[ni][0] = SBh[(n + grp) * 20 + k0 + tg];
                bh[ni][1] = SBh[(n + grp) * 20 + k0 + tg + 4];
                bl[ni][0] = SBl[(n + grp) * 20 + k0 + tg];
                bl[ni][1] = SBl[(n + grp) * 20 + k0 + tg + 4];
            }
#pragma unroll
            for (int mi = 0; mi < 4; mi++)
#pragma unroll
                for (int ni = 0; ni < 4; ni++) {
                    mma_tf32(c[mi][ni], ah[mi], bh[ni]);
                    mma_tf32(c[mi][ni], ah[mi], bl[ni]);
                    mma_tf32(c[mi][ni], al[mi], bh[ni]);
                }
        }
        __syncthreads();
    }

#pragma unroll
    for (int mi = 0; mi < 4; mi++)
#pragma unroll
        for (int ni = 0; ni < 4; ni++) {
            int r   = row0 + wm * 64 + mi * 16 + grp;
            int cix = col0 + wn * 32 + ni * 8 + tg * 2;
            *(float2*)(g_w + (size_t)r * GG + cix)       = make_float2(c[mi][ni][0], c[mi][ni][1]);
            *(float2*)(g_w + (size_t)(r + 8) * GG + cix) = make_float2(c[mi][ni][2], c[mi][ni][3]);
        }
#undef LOAD_TILE
}

// ---------------- batch-norm stats (deterministic two-stage) ----------------
__global__ void stats_partial_kernel()
{
    int col = blockIdx.x * 256 + threadIdx.x;
    int r0  = blockIdx.y * 128;
    float s = 0.f, q = 0.f;
    for (int i = 0; i < 128; i++) {
        float v = g_w[(size_t)(r0 + i) * GG + col];
        s += v;
        q += v * v;
    }
    g_psum[blockIdx.y * GG + col] = s;
    g_psq [blockIdx.y * GG + col] = q;
}

__global__ void stats_final_kernel(const float* __restrict__ gamma,
                                   const float* __restrict__ beta)
{
    int col = blockIdx.x * 256 + threadIdx.x;
    float s = 0.f, q = 0.f;
    for (int i = 0; i < 125; i++) {
        s += g_psum[i * GG + col];
        q += g_psq [i * GG + col];
    }
    float mean = s * (1.f / 16000.f);
    float var  = q * (1.f / 16000.f) - mean * mean;
    float sc   = gamma[col] * rsqrtf(var + 1e-5f);
    g_scale[col] = sc;
    g_shift[col] = beta[col] - mean * sc;
}

// ---------------- normalize + transpose: g_wT[t][g][b2] ----------------
__global__ __launch_bounds__(256) void normT_kernel()
{
    __shared__ float tile[32][33];
    int g0  = blockIdx.x * 32;
    int t   = blockIdx.y;
    int tid = threadIdx.x;
    {
        int b2 = tid >> 3, gq = (tid & 7) * 4;
        float4 v = *(const float4*)(g_w + (size_t)(b2 * TT + t) * GG + g0 + gq);
        tile[b2][gq + 0] = v.x; tile[b2][gq + 1] = v.y;
        tile[b2][gq + 2] = v.z; tile[b2][gq + 3] = v.w;
    }
    __syncthreads();
    {
        int gr = tid >> 3, bq = (tid & 7) * 4;
        float sc = g_scale[g0 + gr], sh = g_shift[g0 + gr];
        float4 o;
        o.x = tile[bq + 0][gr] * sc + sh;
        o.y = tile[bq + 1][gr] * sc + sh;
        o.z = tile[bq + 2][gr] * sc + sh;
        o.w = tile[bq + 3][gr] * sc + sh;
        *(float4*)(g_wT + ((size_t)t * GG + g0 + gr) * B2 + bq) = o;
    }
}

__global__ void reset_bar_kernel() { g_bar = 0u; }

// ---------------- persistent recurrence v5: tensor-core MMA ----------------
// 128 blocks (1/SM), 256 threads = 8 warps. Block owns h-cols blk*8..+7,
// i.e. U rows: A(16 x 1024) = [a-rows 0..7 | z-rows 8..15].
// Warp w owns k-slice [128w, +128): its U A-fragments (hi+lo tf32) live in
// REGISTERS for the whole kernel. Per step: warp cp.asyncs its own h slice
// (f32) into stride-40 conflict-free smem, converts to tf32 hi/lo on the fly,
// does 16kt x 4nt x 3 MMAs (m16n8k8). Partials reduced through smem; thread
// (w,lane) finalizes (col = lane>>2, batch = (w&3)*8 + 2*(lane&3) + (w>>2)).
#define HSTRIDE 40
#define REC_SMEM ((1024 * HSTRIDE + 8 * 16 * 32) * 4)   // 180224 B

__device__ __forceinline__ void bar_arrive()
{
    asm volatile("red.release.gpu.global.add.u32 [%0], 1;"
                 :: "l"(&g_bar) : "memory");
}
__device__ __forceinline__ void bar_wait(unsigned target)
{
    unsigned v;
    do {
        asm volatile("ld.acquire.gpu.global.u32 %0, [%1];"
                     : "=r"(v) : "l"(&g_bar) : "memory");
    } while (v < target);
}

__global__ __launch_bounds__(256, 1) void recur_kernel(const float* __restrict__ U,
                                                       float* __restrict__ out,
                                                       int layer)
{
    extern __shared__ float sm[];
    float* Hs = sm;                       // 1024 * 40 staged h, [k][b] stride 40
    float* Pa = sm + 1024 * HSTRIDE;      // 8*16*32 partial C exchange

    const int tid  = threadIdx.x;
    const int blk  = blockIdx.x;
    const int w    = tid >> 5;
    const int lane = tid & 31;
    const int grp  = lane >> 2;           // g: A-row group / C-row
    const int tg   = lane & 3;            // k-within-8 / C-col-pair
    const int k0   = w * 128;

    // ---- one-time: U A-fragments into registers (hi+lo tf32) ----
    unsigned Uh[16][4], Ul[16][4];
    {
        const float* ua = U + (size_t)(blk * 8 + grp) * HH;        // a-row
        const float* uz = U + (size_t)(HH + blk * 8 + grp) * HH;   // z-row
#pragma unroll
        for (int kt = 0; kt < 16; kt++) {
            int kb = k0 + kt * 8;
            tf32split(ua[kb + tg],     Uh[kt][0], Ul[kt][0]);
            tf32split(uz[kb + tg],     Uh[kt][1], Ul[kt][1]);
            tf32split(ua[kb + tg + 4], Uh[kt][2], Ul[kt][2]);
            tf32split(uz[kb + tg + 4], Uh[kt][3], Ul[kt][3]);
        }
    }

    // zero h parity 0 (128*256 = HS exactly)
    g_h[blk * 256 + tid] = 0.f;

    __syncthreads();
    if (tid == 0) { bar_arrive(); bar_wait(gridDim.x); }
    __syncthreads();

    const int nt  = w & 3;                 // finalized n-tile
    const int par = w >> 2;                // even/odd batch within pair
    const int bfin = nt * 8 + 2 * tg + par; // finalized batch
    const int gac  = blk * 8 + grp;         // finalized h-column
    float hp = 0.f;

    const unsigned hs_base = (unsigned)__cvta_generic_to_shared(Hs);

#define INNER(KT) do {                                                        \
        const float* r0p = Hs + (k0 + (KT) * 8 + tg) * HSTRIDE;               \
        const float* r1p = r0p + 4 * HSTRIDE;                                 \
        _Pragma("unroll")                                                     \
        for (int q = 0; q < 4; q++) {                                         \
            float h0 = r0p[q * 8 + grp];                                      \
            float h1 = r1p[q * 8 + grp];                                      \
            unsigned bh[2], bl[2];                                            \
            asm("cvt.rna.tf32.f32 %0, %1;" : "=r"(bh[0]) : "f"(h0));          \
            asm("cvt.rna.tf32.f32 %0, %1;" : "=r"(bh[1]) : "f"(h1));          \
            float l0 = h0 - __uint_as_float(bh[0]);                           \
            float l1 = h1 - __uint_as_float(bh[1]);                           \
            asm("cvt.rna.tf32.f32 %0, %1;" : "=r"(bl[0]) : "f"(l0));          \
            asm("cvt.rna.tf32.f32 %0, %1;" : "=r"(bl[1]) : "f"(l1));          \
            mma_tf32(acc + q * 4, Uh[KT], bh);                                \
            mma_tf32(acc + q * 4, Ul[KT], bh);                                \
            mma_tf32(acc + q * 4, Uh[KT], bl);                                \
        }                                                                     \
    } while (0)

    for (int t = 0; t < TT; t++) {
        const int cur = t & 1;
        const int nxt = cur ^ 1;

        // ---- stage this warp's own h slice (f32), 2 committed halves ----
        const float* hsrc = g_h + cur * HS;
#pragma unroll
        for (int half = 0; half < 2; half++) {
#pragma unroll
            for (int i = 0; i < 16; i++) {
                int idx = half * 512 + i * 32 + lane;   // 0..1023 float4s
                int row = idx >> 3, ch = idx & 7;
                cp16(hs_base + ((k0 + row) * HSTRIDE + ch * 4) * 4,
                     hsrc + (k0 + row) * 32 + ch * 4);
            }
            asm volatile("cp.async.commit_group;");
        }

        float acc[16];
#pragma unroll
        for (int i = 0; i < 16; i++) acc[i] = 0.f;

        asm volatile("cp.async.wait_group 1;");
        INNER(0); INNER(1); INNER(2); INNER(3);
        INNER(4); INNER(5); INNER(6); INNER(7);
        asm volatile("cp.async.wait_group 0;");
        INNER(8); INNER(9); INNER(10); INNER(11);
        INNER(12); INNER(13); INNER(14); INNER(15);

        // ---- exchange partials ----
#pragma unroll
        for (int r = 0; r < 16; r++)
            Pa[(w * 16 + r) * 32 + lane] = acc[r];
        __syncthreads();

        // ---- finalize (col gac, batch bfin) ----
        float a_t = g_wT[((size_t)t * GG + gac) * 32 + bfin];
        float z_t = g_wT[((size_t)t * GG + HH + gac) * 32 + bfin];
        const int ra = nt * 4 + par;
        const int rz = nt * 4 + 2 + par;
#pragma unroll
        for (int sw = 0; sw < 8; sw++) {
            a_t += Pa[(sw * 16 + ra) * 32 + lane];
            z_t += Pa[(sw * 16 + rz) * 32 + lane];
        }
        float z  = 1.f / (1.f + expf(-z_t));
        float hn = z * hp + (1.f - z) * fmaxf(a_t, 0.f);
        hp = hn;
        g_h[nxt * HS + gac * 32 + bfin] = hn;

        // ---- barrier (output store overlapped with poll) ----
        __syncthreads();
        if (tid == 0) bar_arrive();
        if (layer == 0) {
            g_hs0[(size_t)(bfin * TT + t) * HH + gac] = hn;
        } else {
            if (bfin < BB)
                out[(size_t)(bfin * TT + t) * GG + gac] = hn;
            else
                out[(size_t)((bfin - BB) * TT + (TT - 1 - t)) * GG + HH + gac] = hn;
        }
        if (tid == 0) bar_wait((unsigned)(t + 2) * gridDim.x);
        __syncthreads();
    }
#undef INNER
}

// ---------------- launch ----------------
extern "C" void kernel_launch(void* const* d_in, const int* in_sizes, int n_in,
                              void* d_out, int out_size)
{
    const float* x  = (const float*)d_in[0];
    const float* w0 = (const float*)d_in[1];
    const float* u0 = (const float*)d_in[2];
    const float* g0 = (const float*)d_in[3];
    const float* b0 = (const float*)d_in[4];
    const float* w1 = (const float*)d_in[5];
    const float* u1 = (const float*)d_in[6];
    const float* g1 = (const float*)d_in[7];
    const float* b1 = (const float*)d_in[8];
    float* out = (float*)d_out;

    cudaFuncSetAttribute(recur_kernel, cudaFuncAttributeMaxDynamicSharedMemorySize, REC_SMEM);
    cudaFuncSetAttribute(gemm_tf32_kernel, cudaFuncAttributeMaxDynamicSharedMemorySize, GEMM_SMEM);

    dim3 ggrid(GG / 128, NROWS / 128);   // (16, 125)
    dim3 sgrid(GG / 256, 125);           // (8, 125)
    dim3 tgrid(GG / 32, TT);             // (64, 500)

    // ---- layer 0 ----
    convA_kernel<<<NROWS, 256>>>(x, 512, 0);
    convW_kernel<<<(GG * 512) / 1024, 256>>>(w0, GG * 512);
    gemm_tf32_kernel<<<ggrid, 256, GEMM_SMEM>>>(512);
    stats_partial_kernel<<<sgrid, 256>>>();
    stats_final_kernel<<<GG / 256, 256>>>(g0, b0);
    normT_kernel<<<tgrid, 256>>>();
    reset_bar_kernel<<<1, 1>>>();
    recur_kernel<<<128, 256, REC_SMEM>>>(u0, out, 0);

    // ---- layer 1 ----
    convA_kernel<<<NROWS, 256>>>(x, 2048, 1);
    convW_kernel<<<(GG * GG) / 1024, 256>>>(w1, GG * GG);
    gemm_tf32_kernel<<<ggrid, 256, GEMM_SMEM>>>(2048);
    stats_partial_kernel<<<sgrid, 256>>>();
    stats_final_kernel<<<GG / 256, 256>>>(g1, b1);
    normT_kernel<<<tgrid, 256>>>();
    reset_bar_kernel<<<1, 1>>>();
    recur_kernel<<<128, 256, REC_SMEM>>>(u1, out, 1);
}

// round 14
// speedup vs baseline: 1.6614x; 1.0528x over previous
#include <cuda_runtime.h>
#include <math.h>
#include <stdint.h>

// Problem constants
#define BB    16
#define B2    32
#define TT    500
#define HH    1024
#define GG    2048
#define NROWS 16000
#define HS    (HH * B2)

typedef unsigned long long ull;

// ---------------- scratch (device globals; no allocation) ----------------
__device__ __align__(128) float g_w  [(size_t)NROWS * GG];   // raw input projections [r][g]
__device__ __align__(128) float g_hs0[(size_t)B2 * TT * HH]; // layer-0 hidden sequence
__device__ __align__(128) float g_h  [2 * HS];               // double-buffered h, [parity][k][b]
__device__ __align__(128) float g_psum[125 * GG];
__device__ __align__(128) float g_psq [125 * GG];
__device__ float g_scale[GG];
__device__ float g_shift[GG];
__device__ unsigned int g_bar;
// tf32 hi/lo planes for 3xTF32 GEMM
__device__ __align__(128) unsigned g_Ah[(size_t)NROWS * GG];
__device__ __align__(128) unsigned g_Al[(size_t)NROWS * GG];
__device__ __align__(128) unsigned g_Wh[(size_t)GG * GG];
__device__ __align__(128) unsigned g_Wl[(size_t)GG * GG];

// ---------------- helpers ----------------
__device__ __forceinline__ void tf32split(float v, unsigned& hi, unsigned& lo)
{
    asm("cvt.rna.tf32.f32 %0, %1;" : "=r"(hi) : "f"(v));
    float l = v - __uint_as_float(hi);
    asm("cvt.rna.tf32.f32 %0, %1;" : "=r"(lo) : "f"(l));
}

__device__ __forceinline__ void cp16(unsigned int d, const void* s) {
    asm volatile("cp.async.cg.shared.global [%0], [%1], 16;" :: "r"(d), "l"(s));
}

__device__ __forceinline__ void mma_tf32(float* c, const unsigned* a, const unsigned* b)
{
    asm volatile(
        "mma.sync.aligned.m16n8k8.row.col.f32.tf32.tf32.f32 "
        "{%0,%1,%2,%3}, {%4,%5,%6,%7}, {%8,%9}, {%0,%1,%2,%3};"
        : "+f"(c[0]), "+f"(c[1]), "+f"(c[2]), "+f"(c[3])
        : "r"(a[0]), "r"(a[1]), "r"(a[2]), "r"(a[3]), "r"(b[0]), "r"(b[1]));
}

// ---------------- prep: gather A (bidir concat) + tf32 split ----------------
__global__ __launch_bounds__(256) void convA_kernel(const float* __restrict__ X,
                                                    int F, int layer)
{
    int r  = blockIdx.x;
    int b2 = r / TT;
    int t  = r - b2 * TT;
    int b  = b2 & 15;
    int tt = (b2 < BB) ? t : (TT - 1 - t);
    const float* srcF;
    const float* srcB;
    if (layer == 0) {
        srcF = X + (size_t)(b * TT + tt) * 512;
        srcB = srcF;
    } else {
        srcF = g_hs0 + (size_t)(b * TT + tt) * HH;
        srcB = g_hs0 + (size_t)((b + 16) * TT + (TT - 1 - tt)) * HH - HH; // valid for f>=HH
    }
    size_t base = (size_t)r * F;
    for (int f = threadIdx.x; f < F; f += 256) {
        float v = (layer == 0 || f < HH) ? srcF[f] : srcB[f];
        unsigned hi, lo;
        tf32split(v, hi, lo);
        g_Ah[base + f] = hi;
        g_Al[base + f] = lo;
    }
}

__global__ __launch_bounds__(256) void convW_kernel(const float* __restrict__ Wm, int n)
{
    int i = (blockIdx.x * 256 + threadIdx.x) * 4;
    if (i >= n) return;
    float4 v = *(const float4*)(Wm + i);
    unsigned h0, l0, h1, l1, h2, l2, h3, l3;
    tf32split(v.x, h0, l0);
    tf32split(v.y, h1, l1);
    tf32split(v.z, h2, l2);
    tf32split(v.w, h3, l3);
    *(uint4*)(g_Wh + i) = make_uint4(h0, h1, h2, h3);
    *(uint4*)(g_Wl + i) = make_uint4(l0, l1, l2, l3);
}

// ---------------- 3xTF32 GEMM (validated) ----------------
#define PLANE 2560
#define GEMM_SMEM (2 * 4 * PLANE * 4)

__global__ __launch_bounds__(256, 1) void gemm_tf32_kernel(int F)
{
    extern __shared__ unsigned smu[];

    const int tid  = threadIdx.x;
    const int row0 = blockIdx.y * 128;
    const int col0 = blockIdx.x * 128;
    const int w    = tid >> 5;
    const int lane = tid & 31;
    const int grp  = lane >> 2;
    const int tg   = lane & 3;
    const int wm   = w >> 2;
    const int wn   = w & 3;

    const unsigned smbase = (unsigned)__cvta_generic_to_shared(smu);
    const int nt = F / 16;

    float c[4][4][4];
#pragma unroll
    for (int i = 0; i < 4; i++)
#pragma unroll
        for (int j = 0; j < 4; j++)
#pragma unroll
            for (int q = 0; q < 4; q++) c[i][j][q] = 0.f;

#define LOAD_TILE(IT, BUF)                                                           \
    do {                                                                             \
        int kk = (IT) * 16;                                                          \
        unsigned sb = smbase + (BUF) * 4 * PLANE * 4;                                \
        _Pragma("unroll")                                                            \
        for (int p = 0; p < 4; p++) {                                                \
            const unsigned* src = (p == 0) ? g_Ah : (p == 1) ? g_Al                  \
                                  : (p == 2) ? g_Wh : g_Wl;                          \
            size_t gb = (p < 2) ? ((size_t)row0 * F) : ((size_t)col0 * F);           \
            _Pragma("unroll")                                                        \
            for (int rep = 0; rep < 2; rep++) {                                      \
                int idx = rep * 256 + tid;                                           \
                int row = idx >> 2, ch = idx & 3;                                    \
                cp16(sb + p * PLANE * 4 + row * 80 + ch * 16,                        \
                     src + gb + (size_t)row * F + kk + ch * 4);                      \
            }                                                                        \
        }                                                                            \
        asm volatile("cp.async.commit_group;");                                      \
    } while (0)

    LOAD_TILE(0, 0);

    for (int it = 0; it < nt; it++) {
        if (it + 1 < nt) {
            LOAD_TILE(it + 1, (it + 1) & 1);
            asm volatile("cp.async.wait_group 1;");
        } else {
            asm volatile("cp.async.wait_group 0;");
        }
        __syncthreads();

        const unsigned* SA  = smu + (it & 1) * 4 * PLANE;
        const unsigned* SAl = SA + PLANE;
        const unsigned* SBh = SA + 2 * PLANE;
        const unsigned* SBl = SA + 3 * PLANE;

#pragma unroll
        for (int k0 = 0; k0 < 16; k0 += 8) {
            unsigned ah[4][4], al[4][4], bh[4][2], bl[4][2];
#pragma unroll
            for (int mi = 0; mi < 4; mi++) {
                int m = wm * 64 + mi * 16;
                ah[mi][0] = SA [(m + grp)     * 20 + k0 + tg];
                ah[mi][1] = SA [(m + 8 + grp) * 20 + k0 + tg];
                ah[mi][2] = SA [(m + grp)     * 20 + k0 + tg + 4];
                ah[mi][3] = SA [(m + 8 + grp) * 20 + k0 + tg + 4];
                al[mi][0] = SAl[(m + grp)     * 20 + k0 + tg];
                al[mi][1] = SAl[(m + 8 + grp) * 20 + k0 + tg];
                al[mi][2] = SAl[(m + grp)     * 20 + k0 + tg + 4];
                al[mi][3] = SAl[(m + 8 + grp) * 20 + k0 + tg + 4];
            }
#pragma unroll
            for (int ni = 0; ni < 4; ni++) {
                int n = wn * 32 + ni * 8;
                bh[ni][0] = SBh[(n + grp) * 20 + k0 + tg];
                bh[ni][1] = SBh[(n + grp) * 20 + k0 + tg + 4];
                bl[ni][0] = SBl[(n + grp) * 20 + k0 + tg];
                bl[ni][1] = SBl[(n + grp) * 20 + k0 + tg + 4];
            }
#pragma unroll
            for (int mi = 0; mi < 4; mi++)
#pragma unroll
                for (int ni = 0; ni < 4; ni++) {
                    mma_tf32(c[mi][ni], ah[mi], bh[ni]);
                    mma_tf32(c[mi][ni], ah[mi], bl[ni]);
                    mma_tf32(c[mi][ni], al[mi], bh[ni]);
                }
        }
        __syncthreads();
    }

#pragma unroll
    for (int mi = 0; mi < 4; mi++)
#pragma unroll
        for (int ni = 0; ni < 4; ni++) {
            int r   = row0 + wm * 64 + mi * 16 + grp;
            int cix = col0 + wn * 32 + ni * 8 + tg * 2;
            *(float2*)(g_w + (size_t)r * GG + cix)       = make_float2(c[mi][ni][0], c[mi][ni][1]);
            *(float2*)(g_w + (size_t)(r + 8) * GG + cix) = make_float2(c[mi][ni][2], c[mi][ni][3]);
        }
#undef LOAD_TILE
}

// ---------------- batch-norm stats (deterministic two-stage) ----------------
__global__ void stats_partial_kernel()
{
    int col = blockIdx.x * 256 + threadIdx.x;
    int r0  = blockIdx.y * 128;
    float s = 0.f, q = 0.f;
    for (int i = 0; i < 128; i++) {
        float v = g_w[(size_t)(r0 + i) * GG + col];
        s += v;
        q += v * v;
    }
    g_psum[blockIdx.y * GG + col] = s;
    g_psq [blockIdx.y * GG + col] = q;
}

__global__ void stats_final_kernel(const float* __restrict__ gamma,
                                   const float* __restrict__ beta)
{
    int col = blockIdx.x * 256 + threadIdx.x;
    float s = 0.f, q = 0.f;
    for (int i = 0; i < 125; i++) {
        s += g_psum[i * GG + col];
        q += g_psq [i * GG + col];
    }
    float mean = s * (1.f / 16000.f);
    float var  = q * (1.f / 16000.f) - mean * mean;
    float sc   = gamma[col] * rsqrtf(var + 1e-5f);
    g_scale[col] = sc;
    g_shift[col] = beta[col] - mean * sc;
}

__global__ void reset_bar_kernel() { g_bar = 0u; }

// ---------------- persistent recurrence v6: tensor-core MMA ----------------
// As v5 (round 13, validated), plus:
//  - normalization folded in: finalize reads raw g_w + applies per-thread
//    scale/shift constants (g_wT / normT removed)
//  - w contributions prefetched at the TOP of each step (DRAM latency hidden
//    under the MMA compute + exchange window)
//  - 4-chunk cp.async staging (finer L2/compute overlap)
//  - __expf sigmoid
#define HSTRIDE 40
#define REC_SMEM ((1024 * HSTRIDE + 8 * 16 * 32) * 4)   // 180224 B

__device__ __forceinline__ void bar_arrive()
{
    asm volatile("red.release.gpu.global.add.u32 [%0], 1;"
                 :: "l"(&g_bar) : "memory");
}
__device__ __forceinline__ void bar_wait(unsigned target)
{
    unsigned v;
    do {
        asm volatile("ld.acquire.gpu.global.u32 %0, [%1];"
                     : "=r"(v) : "l"(&g_bar) : "memory");
    } while (v < target);
}

__global__ __launch_bounds__(256, 1) void recur_kernel(const float* __restrict__ U,
                                                       float* __restrict__ out,
                                                       int layer)
{
    extern __shared__ float sm[];
    float* Hs = sm;                       // 1024 * 40 staged h, [k][b] stride 40
    float* Pa = sm + 1024 * HSTRIDE;      // 8*16*32 partial C exchange

    const int tid  = threadIdx.x;
    const int blk  = blockIdx.x;
    const int w    = tid >> 5;
    const int lane = tid & 31;
    const int grp  = lane >> 2;           // g: A-row group / C-row
    const int tg   = lane & 3;            // k-within-8 / C-col-pair
    const int k0   = w * 128;

    // ---- one-time: U A-fragments into registers (hi+lo tf32) ----
    unsigned Uh[16][4], Ul[16][4];
    {
        const float* ua = U + (size_t)(blk * 8 + grp) * HH;        // a-row
        const float* uz = U + (size_t)(HH + blk * 8 + grp) * HH;   // z-row
#pragma unroll
        for (int kt = 0; kt < 16; kt++) {
            int kb = k0 + kt * 8;
            tf32split(ua[kb + tg],     Uh[kt][0], Ul[kt][0]);
            tf32split(uz[kb + tg],     Uh[kt][1], Ul[kt][1]);
            tf32split(ua[kb + tg + 4], Uh[kt][2], Ul[kt][2]);
            tf32split(uz[kb + tg + 4], Uh[kt][3], Ul[kt][3]);
        }
    }

    const int nt   = w & 3;                 // finalized n-tile
    const int par  = w >> 2;                // even/odd batch within pair
    const int bfin = nt * 8 + 2 * tg + par; // finalized batch
    const int gac  = blk * 8 + grp;         // finalized h-column
    float hp = 0.f;

    // per-thread normalization constants (column fixed)
    const float sa  = g_scale[gac],      sha = g_shift[gac];
    const float sz  = g_scale[HH + gac], shz = g_shift[HH + gac];
    const float* wa_base = g_w + (size_t)(bfin * TT) * GG + gac;       // + t*GG
    const float* wz_base = wa_base + HH;

    // zero h parity 0 (128*256 = HS exactly)
    g_h[blk * 256 + tid] = 0.f;

    __syncthreads();
    if (tid == 0) { bar_arrive(); bar_wait(gridDim.x); }
    __syncthreads();

    const unsigned hs_base = (unsigned)__cvta_generic_to_shared(Hs);

#define INNER(KT) do {                                                        \
        const float* r0p = Hs + (k0 + (KT) * 8 + tg) * HSTRIDE;               \
        const float* r1p = r0p + 4 * HSTRIDE;                                 \
        _Pragma("unroll")                                                     \
        for (int q = 0; q < 4; q++) {                                         \
            float h0 = r0p[q * 8 + grp];                                      \
            float h1 = r1p[q * 8 + grp];                                      \
            unsigned bh[2], bl[2];                                            \
            asm("cvt.rna.tf32.f32 %0, %1;" : "=r"(bh[0]) : "f"(h0));          \
            asm("cvt.rna.tf32.f32 %0, %1;" : "=r"(bh[1]) : "f"(h1));          \
            float l0 = h0 - __uint_as_float(bh[0]);                           \
            float l1 = h1 - __uint_as_float(bh[1]);                           \
            asm("cvt.rna.tf32.f32 %0, %1;" : "=r"(bl[0]) : "f"(l0));          \
            asm("cvt.rna.tf32.f32 %0, %1;" : "=r"(bl[1]) : "f"(l1));          \
            mma_tf32(acc + q * 4, Uh[KT], bh);                                \
            mma_tf32(acc + q * 4, Ul[KT], bh);                                \
            mma_tf32(acc + q * 4, Uh[KT], bl);                                \
        }                                                                     \
    } while (0)

    for (int t = 0; t < TT; t++) {
        const int cur = t & 1;
        const int nxt = cur ^ 1;

        // ---- prefetch raw w contributions (consumed in finalize ~2k cyc later)
        float wa = __ldcg(wa_base + (size_t)t * GG);
        float wz = __ldcg(wz_base + (size_t)t * GG);

        // ---- stage this warp's own h slice (f32), 4 committed chunks ----
        const float* hsrc = g_h + cur * HS;
#pragma unroll
        for (int cch = 0; cch < 4; cch++) {
#pragma unroll
            for (int i = 0; i < 8; i++) {
                int idx = cch * 256 + i * 32 + lane;    // 0..1023 float4s
                int row = idx >> 3, ch = idx & 7;
                cp16(hs_base + ((k0 + row) * HSTRIDE + ch * 4) * 4,
                     hsrc + (k0 + row) * 32 + ch * 4);
            }
            asm volatile("cp.async.commit_group;");
        }

        float acc[16];
#pragma unroll
        for (int i = 0; i < 16; i++) acc[i] = 0.f;

        asm volatile("cp.async.wait_group 3;");
        INNER(0); INNER(1); INNER(2); INNER(3);
        asm volatile("cp.async.wait_group 2;");
        INNER(4); INNER(5); INNER(6); INNER(7);
        asm volatile("cp.async.wait_group 1;");
        INNER(8); INNER(9); INNER(10); INNER(11);
        asm volatile("cp.async.wait_group 0;");
        INNER(12); INNER(13); INNER(14); INNER(15);

        // ---- exchange partials ----
#pragma unroll
        for (int r = 0; r < 16; r++)
            Pa[(w * 16 + r) * 32 + lane] = acc[r];
        __syncthreads();

        // ---- finalize (col gac, batch bfin) ----
        float a_t = fmaf(wa, sa, sha);
        float z_t = fmaf(wz, sz, shz);
        const int ra = nt * 4 + par;
        const int rz = nt * 4 + 2 + par;
#pragma unroll
        for (int sw = 0; sw < 8; sw++) {
            a_t += Pa[(sw * 16 + ra) * 32 + lane];
            z_t += Pa[(sw * 16 + rz) * 32 + lane];
        }
        float z  = 1.f / (1.f + __expf(-z_t));
        float hn = z * hp + (1.f - z) * fmaxf(a_t, 0.f);
        hp = hn;
        g_h[nxt * HS + gac * 32 + bfin] = hn;

        // ---- barrier (output store overlapped with poll) ----
        __syncthreads();
        if (tid == 0) bar_arrive();
        if (layer == 0) {
            g_hs0[(size_t)(bfin * TT + t) * HH + gac] = hn;
        } else {
            if (bfin < BB)
                out[(size_t)(bfin * TT + t) * GG + gac] = hn;
            else
                out[(size_t)((bfin - BB) * TT + (TT - 1 - t)) * GG + HH + gac] = hn;
        }
        if (tid == 0) bar_wait((unsigned)(t + 2) * gridDim.x);
        __syncthreads();
    }
#undef INNER
}

// ---------------- launch ----------------
extern "C" void kernel_launch(void* const* d_in, const int* in_sizes, int n_in,
                              void* d_out, int out_size)
{
    const float* x  = (const float*)d_in[0];
    const float* w0 = (const float*)d_in[1];
    const float* u0 = (const float*)d_in[2];
    const float* g0 = (const float*)d_in[3];
    const float* b0 = (const float*)d_in[4];
    const float* w1 = (const float*)d_in[5];
    const float* u1 = (const float*)d_in[6];
    const float* g1 = (const float*)d_in[7];
    const float* b1 = (const float*)d_in[8];
    float* out = (float*)d_out;

    cudaFuncSetAttribute(recur_kernel, cudaFuncAttributeMaxDynamicSharedMemorySize, REC_SMEM);
    cudaFuncSetAttribute(gemm_tf32_kernel, cudaFuncAttributeMaxDynamicSharedMemorySize, GEMM_SMEM);

    dim3 ggrid(GG / 128, NROWS / 128);   // (16, 125)
    dim3 sgrid(GG / 256, 125);           // (8, 125)

    // ---- layer 0 ----
    convA_kernel<<<NROWS, 256>>>(x, 512, 0);
    convW_kernel<<<(GG * 512) / 1024, 256>>>(w0, GG * 512);
    gemm_tf32_kernel<<<ggrid, 256, GEMM_SMEM>>>(512);
    stats_partial_kernel<<<sgrid, 256>>>();
    stats_final_kernel<<<GG / 256, 256>>>(g0, b0);
    reset_bar_kernel<<<1, 1>>>();
    recur_kernel<<<128, 256, REC_SMEM>>>(u0, out, 0);

    // ---- layer 1 ----
    convA_kernel<<<NROWS, 256>>>(x, 2048, 1);
    convW_kernel<<<(GG * GG) / 1024, 256>>>(w1, GG * GG);
    gemm_tf32_kernel<<<ggrid, 256, GEMM_SMEM>>>(2048);
    stats_partial_kernel<<<sgrid, 256>>>();
    stats_final_kernel<<<GG / 256, 256>>>(g1, b1);
    reset_bar_kernel<<<1, 1>>>();
    recur_kernel<<<128, 256, REC_SMEM>>>(u1, out, 1);
}

// round 15
// speedup vs baseline: 2.1471x; 1.2923x over previous
#include <cuda_runtime.h>
#include <math.h>
#include <stdint.h>

// Problem constants
#define BB    16
#define B2    32
#define TT    500
#define HH    1024
#define GG    2048
#define NROWS 16000
#define HS    (HH * B2)

typedef unsigned long long ull;

// ---------------- scratch (device globals; no allocation) ----------------
__device__ __align__(128) float g_w  [(size_t)NROWS * GG];   // raw input projections [r][g]
__device__ __align__(128) float g_hs0[(size_t)B2 * TT * HH]; // layer-0 hidden sequence
__device__ __align__(128) unsigned short g_hb[2][2][B2][HH]; // h transport: [parity][hi/lo][b][k] bf16
__device__ __align__(128) float g_psum[125 * GG];
__device__ __align__(128) float g_psq [125 * GG];
__device__ float g_scale[GG];
__device__ float g_shift[GG];
__device__ unsigned int g_bar;
// tf32 hi/lo planes for 3xTF32 GEMM
__device__ __align__(128) unsigned g_Ah[(size_t)NROWS * GG];
__device__ __align__(128) unsigned g_Al[(size_t)NROWS * GG];
__device__ __align__(128) unsigned g_Wh[(size_t)GG * GG];
__device__ __align__(128) unsigned g_Wl[(size_t)GG * GG];

// ---------------- helpers ----------------
__device__ __forceinline__ void tf32split(float v, unsigned& hi, unsigned& lo)
{
    asm("cvt.rna.tf32.f32 %0, %1;" : "=r"(hi) : "f"(v));
    float l = v - __uint_as_float(hi);
    asm("cvt.rna.tf32.f32 %0, %1;" : "=r"(lo) : "f"(l));
}

__device__ __forceinline__ void cp16(unsigned int d, const void* s) {
    asm volatile("cp.async.cg.shared.global [%0], [%1], 16;" :: "r"(d), "l"(s));
}

__device__ __forceinline__ void mma_tf32(float* c, const unsigned* a, const unsigned* b)
{
    asm volatile(
        "mma.sync.aligned.m16n8k8.row.col.f32.tf32.tf32.f32 "
        "{%0,%1,%2,%3}, {%4,%5,%6,%7}, {%8,%9}, {%0,%1,%2,%3};"
        : "+f"(c[0]), "+f"(c[1]), "+f"(c[2]), "+f"(c[3])
        : "r"(a[0]), "r"(a[1]), "r"(a[2]), "r"(a[3]), "r"(b[0]), "r"(b[1]));
}

__device__ __forceinline__ void mma_bf16(float* c, const unsigned* a, unsigned b0, unsigned b1)
{
    asm volatile(
        "mma.sync.aligned.m16n8k16.row.col.f32.bf16.bf16.f32 "
        "{%0,%1,%2,%3}, {%4,%5,%6,%7}, {%8,%9}, {%0,%1,%2,%3};"
        : "+f"(c[0]), "+f"(c[1]), "+f"(c[2]), "+f"(c[3])
        : "r"(a[0]), "r"(a[1]), "r"(a[2]), "r"(a[3]), "r"(b0), "r"(b1));
}

// pack two f32 into bf16x2 (v0 -> low half / first k, v1 -> high)
__device__ __forceinline__ unsigned pk_bf16x2(float v0, float v1)
{
    unsigned d;
    asm("cvt.rn.bf16x2.f32 %0, %1, %2;" : "=r"(d) : "f"(v1), "f"(v0));
    return d;
}

// ---------------- prep: gather A (bidir concat) + tf32 split ----------------
__global__ __launch_bounds__(256) void convA_kernel(const float* __restrict__ X,
                                                    int F, int layer)
{
    int r  = blockIdx.x;
    int b2 = r / TT;
    int t  = r - b2 * TT;
    int b  = b2 & 15;
    int tt = (b2 < BB) ? t : (TT - 1 - t);
    const float* srcF;
    const float* srcB;
    if (layer == 0) {
        srcF = X + (size_t)(b * TT + tt) * 512;
        srcB = srcF;
    } else {
        srcF = g_hs0 + (size_t)(b * TT + tt) * HH;
        srcB = g_hs0 + (size_t)((b + 16) * TT + (TT - 1 - tt)) * HH - HH; // valid for f>=HH
    }
    size_t base = (size_t)r * F;
    for (int f = threadIdx.x; f < F; f += 256) {
        float v = (layer == 0 || f < HH) ? srcF[f] : srcB[f];
        unsigned hi, lo;
        tf32split(v, hi, lo);
        g_Ah[base + f] = hi;
        g_Al[base + f] = lo;
    }
}

__global__ __launch_bounds__(256) void convW_kernel(const float* __restrict__ Wm, int n)
{
    int i = (blockIdx.x * 256 + threadIdx.x) * 4;
    if (i >= n) return;
    float4 v = *(const float4*)(Wm + i);
    unsigned h0, l0, h1, l1, h2, l2, h3, l3;
    tf32split(v.x, h0, l0);
    tf32split(v.y, h1, l1);
    tf32split(v.z, h2, l2);
    tf32split(v.w, h3, l3);
    *(uint4*)(g_Wh + i) = make_uint4(h0, h1, h2, h3);
    *(uint4*)(g_Wl + i) = make_uint4(l0, l1, l2, l3);
}

// ---------------- 3xTF32 GEMM (validated) ----------------
#define PLANE 2560
#define GEMM_SMEM (2 * 4 * PLANE * 4)

__global__ __launch_bounds__(256, 1) void gemm_tf32_kernel(int F)
{
    extern __shared__ unsigned smu[];

    const int tid  = threadIdx.x;
    const int row0 = blockIdx.y * 128;
    const int col0 = blockIdx.x * 128;
    const int w    = tid >> 5;
    const int lane = tid & 31;
    const int grp  = lane >> 2;
    const int tg   = lane & 3;
    const int wm   = w >> 2;
    const int wn   = w & 3;

    const unsigned smbase = (unsigned)__cvta_generic_to_shared(smu);
    const int nt = F / 16;

    float c[4][4][4];
#pragma unroll
    for (int i = 0; i < 4; i++)
#pragma unroll
        for (int j = 0; j < 4; j++)
#pragma unroll
            for (int q = 0; q < 4; q++) c[i][j][q] = 0.f;

#define LOAD_TILE(IT, BUF)                                                           \
    do {                                                                             \
        int kk = (IT) * 16;                                                          \
        unsigned sb = smbase + (BUF) * 4 * PLANE * 4;                                \
        _Pragma("unroll")                                                            \
        for (int p = 0; p < 4; p++) {                                                \
            const unsigned* src = (p == 0) ? g_Ah : (p == 1) ? g_Al                  \
                                  : (p == 2) ? g_Wh : g_Wl;                          \
            size_t gb = (p < 2) ? ((size_t)row0 * F) : ((size_t)col0 * F);           \
            _Pragma("unroll")                                                        \
            for (int rep = 0; rep < 2; rep++) {                                      \
                int idx = rep * 256 + tid;                                           \
                int row = idx >> 2, ch = idx & 3;                                    \
                cp16(sb + p * PLANE * 4 + row * 80 + ch * 16,                        \
                     src + gb + (size_t)row * F + kk + ch * 4);                      \
            }                                                                        \
        }                                                                            \
        asm volatile("cp.async.commit_group;");                                      \
    } while (0)

    LOAD_TILE(0, 0);

    for (int it = 0; it < nt; it++) {
        if (it + 1 < nt) {
            LOAD_TILE(it + 1, (it + 1) & 1);
            asm volatile("cp.async.wait_group 1;");
        } else {
            asm volatile("cp.async.wait_group 0;");
        }
        __syncthreads();

        const unsigned* SA  = smu + (it & 1) * 4 * PLANE;
        const unsigned* SAl = SA + PLANE;
        const unsigned* SBh = SA + 2 * PLANE;
        const unsigned* SBl = SA + 3 * PLANE;

#pragma unroll
        for (int k0 = 0; k0 < 16; k0 += 8) {
            unsigned ah[4][4], al[4][4], bh[4][2], bl[4][2];
#pragma unroll
            for (int mi = 0; mi < 4; mi++) {
                int m = wm * 64 + mi * 16;
                ah[mi][0] = SA [(m + grp)     * 20 + k0 + tg];
                ah[mi][1] = SA [(m + 8 + grp) * 20 + k0 + tg];
                ah[mi][2] = SA [(m + grp)     * 20 + k0 + tg + 4];
                ah[mi][3] = SA [(m + 8 + grp) * 20 + k0 + tg + 4];
                al[mi][0] = SAl[(m + grp)     * 20 + k0 + tg];
                al[mi][1] = SAl[(m + 8 + grp) * 20 + k0 + tg];
                al[mi][2] = SAl[(m + grp)     * 20 + k0 + tg + 4];
                al[mi][3] = SAl[(m + 8 + grp) * 20 + k0 + tg + 4];
            }
#pragma unroll
            for (int ni = 0; ni < 4; ni++) {
                int n = wn * 32 + ni * 8;
                bh[ni][0] = SBh[(n + grp) * 20 + k0 + tg];
                bh[ni][1] = SBh[(n + grp) * 20 + k0 + tg + 4];
                bl[ni][0] = SBl[(n + grp) * 20 + k0 + tg];
                bl[ni][1] = SBl[(n + grp) * 20 + k0 + tg + 4];
            }
#pragma unroll
            for (int mi = 0; mi < 4; mi++)
#pragma unroll
                for (int ni = 0; ni < 4; ni++) {
                    mma_tf32(c[mi][ni], ah[mi], bh[ni]);
                    mma_tf32(c[mi][ni], ah[mi], bl[ni]);
                    mma_tf32(c[mi][ni], al[mi], bh[ni]);
                }
        }
        __syncthreads();
    }

#pragma unroll
    for (int mi = 0; mi < 4; mi++)
#pragma unroll
        for (int ni = 0; ni < 4; ni++) {
            int r   = row0 + wm * 64 + mi * 16 + grp;
            int cix = col0 + wn * 32 + ni * 8 + tg * 2;
            *(float2*)(g_w + (size_t)r * GG + cix)       = make_float2(c[mi][ni][0], c[mi][ni][1]);
            *(float2*)(g_w + (size_t)(r + 8) * GG + cix) = make_float2(c[mi][ni][2], c[mi][ni][3]);
        }
#undef LOAD_TILE
}

// ---------------- batch-norm stats (deterministic two-stage) ----------------
__global__ void stats_partial_kernel()
{
    int col = blockIdx.x * 256 + threadIdx.x;
    int r0  = blockIdx.y * 128;
    float s = 0.f, q = 0.f;
    for (int i = 0; i < 128; i++) {
        float v = g_w[(size_t)(r0 + i) * GG + col];
        s += v;
        q += v * v;
    }
    g_psum[blockIdx.y * GG + col] = s;
    g_psq [blockIdx.y * GG + col] = q;
}

__global__ void stats_final_kernel(const float* __restrict__ gamma,
                                   const float* __restrict__ beta)
{
    int col = blockIdx.x * 256 + threadIdx.x;
    float s = 0.f, q = 0.f;
    for (int i = 0; i < 125; i++) {
        s += g_psum[i * GG + col];
        q += g_psq [i * GG + col];
    }
    float mean = s * (1.f / 16000.f);
    float var  = q * (1.f / 16000.f) - mean * mean;
    float sc   = gamma[col] * rsqrtf(var + 1e-5f);
    g_scale[col] = sc;
    g_shift[col] = beta[col] - mean * sc;
}

__global__ void reset_bar_kernel() { g_bar = 0u; }

// ---------------- persistent recurrence v7: bf16 hi/lo MMA, 2D split ----------------
// 128 blocks = 64 col-groups x 2 batch-groups, 256 threads = 8 warps.
// Block (colg, bg): owns h-cols [colg*16,+16) (A = 32 gate rows: 16 a + 16 z
// = two m16 tiles) and batches [bg*16,+16). U fragments (bf16 hi+lo) in
// registers. Per step: warp w stages its k-slice [128w,+128) of BOTH bf16
// planes for the block's 16 batches ([b][k] layout -> B-fragments are direct
// LDS.32). 3-term bf16 MMA (Uh*bh + Ul*bh + Uh*bl). One exchange sync;
// one (col,batch) finalized per thread.
#define HROW 1032                           // u16 per smem row (1024 + 8 pad)
#define REC_SMEM (2 * 16 * HROW * 2 + 8 * 16 * 32 * 4)   // 82432 B

__device__ __forceinline__ void bar_arrive()
{
    asm volatile("red.release.gpu.global.add.u32 [%0], 1;"
                 :: "l"(&g_bar) : "memory");
}
__device__ __forceinline__ void bar_wait(unsigned target)
{
    unsigned v;
    do {
        asm volatile("ld.acquire.gpu.global.u32 %0, [%1];"
                     : "=r"(v) : "l"(&g_bar) : "memory");
    } while (v < target);
}

__global__ __launch_bounds__(256, 1) void recur_kernel(const float* __restrict__ U,
                                                       float* __restrict__ out,
                                                       int layer)
{
    extern __shared__ unsigned short smh[];
    unsigned short* Hs = smh;                          // [plane][b_local][HROW]
    float* Pa = (float*)(smh + 2 * 16 * HROW);         // 8*16*32 partials

    const int tid  = threadIdx.x;
    const int blk  = blockIdx.x;
    const int colg = blk >> 1;            // 0..63
    const int bg   = blk & 1;             // batch group
    const int w    = tid >> 5;
    const int lane = tid & 31;
    const int grp  = lane >> 2;
    const int tg   = lane & 3;
    const int k0   = w * 128;

    // ---- one-time: U fragments (bf16 hi+lo) into registers ----
    // mt 0 = a-rows (cols colg*16..+15), mt 1 = z-rows
    unsigned Uh[2][8][4], Ul[2][8][4];
#pragma unroll
    for (int mt = 0; mt < 2; mt++) {
        const float* u0 = U + (size_t)(mt * HH + colg * 16 + grp) * HH;      // row grp
        const float* u1 = u0 + 8 * HH;                                       // row grp+8
#pragma unroll
        for (int kc = 0; kc < 8; kc++) {
            int k = k0 + kc * 16;
#pragma unroll
            for (int half = 0; half < 2; half++) {
                int kk = k + 2 * tg + 8 * half;
                float a00 = u0[kk], a01 = u0[kk + 1];
                float a10 = u1[kk], a11 = u1[kk + 1];
                unsigned h0 = pk_bf16x2(a00, a01);
                unsigned h1 = pk_bf16x2(a10, a11);
                Uh[mt][kc][0 + half * 2] = h0;
                Uh[mt][kc][1 + half * 2] = h1;
                float r00 = a00 - __uint_as_float(h0 << 16);
                float r01 = a01 - __uint_as_float(h0 & 0xffff0000u);
                float r10 = a10 - __uint_as_float(h1 << 16);
                float r11 = a11 - __uint_as_float(h1 & 0xffff0000u);
                Ul[mt][kc][0 + half * 2] = pk_bf16x2(r00, r01);
                Ul[mt][kc][1 + half * 2] = pk_bf16x2(r10, r11);
            }
        }
    }

    // finalized output: one (col, batch) per thread
    const int rb   = w & 1;
    const int ntf  = (w >> 1) & 1;
    const int cb   = w >> 2;
    const int gac  = colg * 16 + grp + 8 * rb;          // global h-col
    const int bfin = bg * 16 + ntf * 8 + 2 * tg + cb;   // global batch
    const int ia   = (0 * 2 + ntf) * 4 + rb * 2 + cb;   // a-entry in exchange
    const int iz   = (1 * 2 + ntf) * 4 + rb * 2 + cb;   // z-entry
    float hp = 0.f;

    const float sa  = g_scale[gac],      sha = g_shift[gac];
    const float sz  = g_scale[HH + gac], shz = g_shift[HH + gac];
    const float* wa_base = g_w + (size_t)(bfin * TT) * GG + gac;
    const float* wz_base = wa_base + HH;

    // zero h parity 0 (both planes): 32768 u32 = 131072 B exactly
    ((unsigned*)g_hb)[blk * 256 + tid] = 0u;

    __syncthreads();
    if (tid == 0) { bar_arrive(); bar_wait(gridDim.x); }
    __syncthreads();

    const unsigned hs_base = (unsigned)__cvta_generic_to_shared(Hs);

    for (int t = 0; t < TT; t++) {
        const int cur = t & 1;
        const int nxt = cur ^ 1;

        // prefetch raw w contributions
        float wa = __ldcg(wa_base + (size_t)t * GG);
        float wz = __ldcg(wz_base + (size_t)t * GG);

        // ---- stage this warp's k-slice of both planes, 16 local batches ----
        // chunk c: c0 = hi b0-7, c1 = hi b8-15, c2 = lo b0-7, c3 = lo b8-15
        const unsigned short* hsrc = &g_hb[cur][0][0][0];
#pragma unroll
        for (int c = 0; c < 4; c++) {
#pragma unroll
            for (int i2 = 0; i2 < 4; i2++) {
                int idx = (c * 4 + i2) * 32 + lane;    // 0..511
                int pl = idx >> 8, rem = idx & 255;
                int bl = rem >> 4, ch = rem & 15;
                cp16(hs_base + ((pl * 16 + bl) * HROW) * 2 + w * 256 + ch * 16,
                     hsrc + (size_t)pl * (B2 * HH) + (size_t)(bg * 16 + bl) * HH + k0 + ch * 8);
            }
            asm volatile("cp.async.commit_group;");
        }

        float acc[16];
#pragma unroll
        for (int i = 0; i < 16; i++) acc[i] = 0.f;

        // B-fragment address helper: plane pl, local batch row br, kchunk kc
#define BLD(pl, br, kc, b0, b1)                                                      \
        do {                                                                          \
            const unsigned short* p_ = Hs + ((pl) * 16 + (br)) * HROW + k0 + (kc) * 16; \
            b0 = *(const unsigned*)(p_ + 2 * tg);                                     \
            b1 = *(const unsigned*)(p_ + 2 * tg + 8);                                 \
        } while (0)

        asm volatile("cp.async.wait_group 3;");   // hi, b0-7 (nt=0)
#pragma unroll
        for (int kc = 0; kc < 8; kc++) {
            unsigned b0, b1; BLD(0, grp, kc, b0, b1);
            mma_bf16(acc + 0,  Uh[0][kc], b0, b1);
            mma_bf16(acc + 8,  Uh[1][kc], b0, b1);
            mma_bf16(acc + 0,  Ul[0][kc], b0, b1);
            mma_bf16(acc + 8,  Ul[1][kc], b0, b1);
        }
        asm volatile("cp.async.wait_group 2;");   // hi, b8-15 (nt=1)
#pragma unroll
        for (int kc = 0; kc < 8; kc++) {
            unsigned b0, b1; BLD(0, 8 + grp, kc, b0, b1);
            mma_bf16(acc + 4,  Uh[0][kc], b0, b1);
            mma_bf16(acc + 12, Uh[1][kc], b0, b1);
            mma_bf16(acc + 4,  Ul[0][kc], b0, b1);
            mma_bf16(acc + 12, Ul[1][kc], b0, b1);
        }
        asm volatile("cp.async.wait_group 1;");   // lo, b0-7
#pragma unroll
        for (int kc = 0; kc < 8; kc++) {
            unsigned b0, b1; BLD(1, grp, kc, b0, b1);
            mma_bf16(acc + 0,  Uh[0][kc], b0, b1);
            mma_bf16(acc + 8,  Uh[1][kc], b0, b1);
        }
        asm volatile("cp.async.wait_group 0;");   // lo, b8-15
#pragma unroll
        for (int kc = 0; kc < 8; kc++) {
            unsigned b0, b1; BLD(1, 8 + grp, kc, b0, b1);
            mma_bf16(acc + 4,  Uh[0][kc], b0, b1);
            mma_bf16(acc + 12, Uh[1][kc], b0, b1);
        }
#undef BLD

        // ---- exchange partials ----
#pragma unroll
        for (int r = 0; r < 16; r++)
            Pa[(w * 16 + r) * 32 + lane] = acc[r];
        __syncthreads();

        // ---- finalize (gac, bfin) ----
        float a_t = fmaf(wa, sa, sha);
        float z_t = fmaf(wz, sz, shz);
#pragma unroll
        for (int sw = 0; sw < 8; sw++) {
            a_t += Pa[(sw * 16 + ia) * 32 + lane];
            z_t += Pa[(sw * 16 + iz) * 32 + lane];
        }
        float z  = 1.f / (1.f + __expf(-z_t));
        float hn = z * hp + (1.f - z) * fmaxf(a_t, 0.f);
        hp = hn;

        // store h transport as bf16 hi + residual
        unsigned short hhi, hlo;
        asm("cvt.rn.bf16.f32 %0, %1;" : "=h"(hhi) : "f"(hn));
        float hr = hn - __uint_as_float((unsigned)hhi << 16);
        asm("cvt.rn.bf16.f32 %0, %1;" : "=h"(hlo) : "f"(hr));
        g_hb[nxt][0][bfin][gac] = hhi;
        g_hb[nxt][1][bfin][gac] = hlo;

        // ---- barrier (f32 output store overlapped with poll) ----
        __syncthreads();
        if (tid == 0) bar_arrive();
        if (layer == 0) {
            g_hs0[(size_t)(bfin * TT + t) * HH + gac] = hn;
        } else {
            if (bfin < BB)
                out[(size_t)(bfin * TT + t) * GG + gac] = hn;
            else
                out[(size_t)((bfin - BB) * TT + (TT - 1 - t)) * GG + HH + gac] = hn;
        }
        if (tid == 0) bar_wait((unsigned)(t + 2) * gridDim.x);
        __syncthreads();
    }
}

// ---------------- launch ----------------
extern "C" void kernel_launch(void* const* d_in, const int* in_sizes, int n_in,
                              void* d_out, int out_size)
{
    const float* x  = (const float*)d_in[0];
    const float* w0 = (const float*)d_in[1];
    const float* u0 = (const float*)d_in[2];
    const float* g0 = (const float*)d_in[3];
    const float* b0 = (const float*)d_in[4];
    const float* w1 = (const float*)d_in[5];
    const float* u1 = (const float*)d_in[6];
    const float* g1 = (const float*)d_in[7];
    const float* b1 = (const float*)d_in[8];
    float* out = (float*)d_out;

    cudaFuncSetAttribute(recur_kernel, cudaFuncAttributeMaxDynamicSharedMemorySize, REC_SMEM);
    cudaFuncSetAttribute(gemm_tf32_kernel, cudaFuncAttributeMaxDynamicSharedMemorySize, GEMM_SMEM);

    dim3 ggrid(GG / 128, NROWS / 128);   // (16, 125)
    dim3 sgrid(GG / 256, 125);           // (8, 125)

    // ---- layer 0 ----
    convA_kernel<<<NROWS, 256>>>(x, 512, 0);
    convW_kernel<<<(GG * 512) / 1024, 256>>>(w0, GG * 512);
    gemm_tf32_kernel<<<ggrid, 256, GEMM_SMEM>>>(512);
    stats_partial_kernel<<<sgrid, 256>>>();
    stats_final_kernel<<<GG / 256, 256>>>(g0, b0);
    reset_bar_kernel<<<1, 1>>>();
    recur_kernel<<<128, 256, REC_SMEM>>>(u0, out, 0);

    // ---- layer 1 ----
    convA_kernel<<<NROWS, 256>>>(x, 2048, 1);
    convW_kernel<<<(GG * GG) / 1024, 256>>>(w1, GG * GG);
    gemm_tf32_kernel<<<ggrid, 256, GEMM_SMEM>>>(2048);
    stats_partial_kernel<<<sgrid, 256>>>();
    stats_final_kernel<<<GG / 256, 256>>>(g1, b1);
    reset_bar_kernel<<<1, 1>>>();
    recur_kernel<<<128, 256, REC_SMEM>>>(u1, out, 1);
}